// round 3
// baseline (speedup 1.0000x reference)
#include <cuda_runtime.h>
#include <cuda_bf16.h>
#include <math.h>

#define LSEQ 512
#define BATCH 32
#define DIN 42
#define HDIM 800
#define G4 3200          // 4*HDIM
#define H2 1600          // 2*HDIM
#define ASZ 20
#define L3 (3*LSEQ)

// ---------------- static device scratch (no allocations allowed) ----------------
// g_G[0]=L0 fwd gates-input, [1]=L0 bwd, [2]=L1 fwd, [3]=L1 bwd : [L][B][3200]
__device__ float g_G[4][LSEQ*BATCH*G4];
__device__ float g_h1[LSEQ*BATCH*H2];
__device__ float g_h2[LSEQ*BATCH*H2];
__device__ float g_hs[2][2][2][BATCH*HDIM];   // [layer][dir][parity][b*H+u]
__device__ float g_cs[2][2][BATCH*HDIM];      // [layer][dir][b*H+u]
__device__ float g_phi[L3*BATCH];             // [3L][B]

// software grid barrier state (count returns to 0 at each barrier; phase is
// monotonic and compared by equality -> deterministic across graph replays)
__device__ unsigned g_barc = 0;
__device__ unsigned g_barp = 0;

__device__ __forceinline__ void grid_sync(unsigned nblocks)
{
    __syncthreads();
    if (threadIdx.x == 0) {
        __threadfence();                                   // release h/c writes
        unsigned gen = *((volatile unsigned*)&g_barp);
        if (atomicAdd(&g_barc, 1u) == nblocks - 1u) {
            g_barc = 0;
            __threadfence();                               // reset before phase bump
            atomicAdd(&g_barp, 1u);
        } else {
            while (*((volatile unsigned*)&g_barp) == gen) { }
        }
        __threadfence();                                   // acquire
    }
    __syncthreads();
}

// ---------------- init: zero LSTM states (graph is replayed; must re-zero) ------
__global__ void k_init()
{
    int i = blockIdx.x * blockDim.x + threadIdx.x;
    if (i < 2*2*2*BATCH*HDIM) ((float*)g_hs)[i] = 0.f;
    if (i < 2*2*BATCH*HDIM)   ((float*)g_cs)[i] = 0.f;
}

// ---------------- layer0 input projection: G = Wih @ x + bih + bhh -------------
__global__ void k_proj0(const float* __restrict__ x,
                        const float* __restrict__ Wf, const float* __restrict__ bif, const float* __restrict__ bhf,
                        const float* __restrict__ Wb, const float* __restrict__ bib, const float* __restrict__ bhb)
{
    int tb  = blockIdx.x;     // 0..L*B-1
    int dir = blockIdx.y;     // 0=f 1=b
    const float* W  = dir ? Wb : Wf;
    const float* b1 = dir ? bib : bif;
    const float* b2 = dir ? bhb : bhf;
    float* G = g_G[dir] + (size_t)tb * G4;

    __shared__ float sx[DIN];
    if (threadIdx.x < DIN) sx[threadIdx.x] = x[(size_t)tb*DIN + threadIdx.x];
    __syncthreads();

    for (int j = threadIdx.x; j < G4; j += blockDim.x) {
        const float* wr = W + (size_t)j * DIN;
        float acc = b1[j] + b2[j];
        #pragma unroll
        for (int k = 0; k < DIN; k++) acc = fmaf(wr[k], sx[k], acc);
        G[j] = acc;
    }
}

// ---------------- layer1 input projection: big SGEMM ---------------------------
// C[16384,3200] = A[16384,1600] * B[3200,1600]^T + (bih+bhh)
#define BM 128
#define BN 128
#define BK 8
__global__ void __launch_bounds__(256)
k_proj1(const float* __restrict__ Wf, const float* __restrict__ bif, const float* __restrict__ bhf,
        const float* __restrict__ Wb, const float* __restrict__ bib, const float* __restrict__ bhb)
{
    int dir = blockIdx.z;
    const float* Bm = dir ? Wb : Wf;
    const float* b1 = dir ? bib : bif;
    const float* b2 = dir ? bhb : bhf;
    const float* A  = g_h1;
    float* C = g_G[2 + dir];

    int m0 = blockIdx.y * BM;
    int n0 = blockIdx.x * BN;

    __shared__ float As[BK][BM];
    __shared__ float Bs[BK][BN];

    int tid = threadIdx.x;           // 256
    int tx = tid & 15, ty = tid >> 4;

    float acc[8][8];
    #pragma unroll
    for (int i = 0; i < 8; i++)
        #pragma unroll
        for (int j = 0; j < 8; j++) acc[i][j] = 0.f;

    int lrow = tid >> 1;             // 0..127
    int lkq  = (tid & 1) * 4;        // 0 or 4

    for (int k0 = 0; k0 < H2; k0 += BK) {
        float4 a4 = *(const float4*)(A  + (size_t)(m0 + lrow)*H2 + k0 + lkq);
        float4 b4 = *(const float4*)(Bm + (size_t)(n0 + lrow)*H2 + k0 + lkq);
        As[lkq+0][lrow] = a4.x; As[lkq+1][lrow] = a4.y; As[lkq+2][lrow] = a4.z; As[lkq+3][lrow] = a4.w;
        Bs[lkq+0][lrow] = b4.x; Bs[lkq+1][lrow] = b4.y; Bs[lkq+2][lrow] = b4.z; Bs[lkq+3][lrow] = b4.w;
        __syncthreads();

        #pragma unroll
        for (int kk = 0; kk < BK; kk++) {
            float af[8], bf[8];
            *(float4*)&af[0] = *(const float4*)&As[kk][ty*8];
            *(float4*)&af[4] = *(const float4*)&As[kk][ty*8+4];
            *(float4*)&bf[0] = *(const float4*)&Bs[kk][tx*8];
            *(float4*)&bf[4] = *(const float4*)&Bs[kk][tx*8+4];
            #pragma unroll
            for (int i = 0; i < 8; i++)
                #pragma unroll
                for (int j = 0; j < 8; j++)
                    acc[i][j] = fmaf(af[i], bf[j], acc[i][j]);
        }
        __syncthreads();
    }

    #pragma unroll
    for (int i = 0; i < 8; i++) {
        int m = m0 + ty*8 + i;
        #pragma unroll
        for (int j = 0; j < 8; j++) {
            int n = n0 + tx*8 + j;
            C[(size_t)m*G4 + n] = acc[i][j] + b1[n] + b2[n];
        }
    }
}

// ---------------- persistent bi-LSTM recurrence for one layer ------------------
// grid: 400 blocks = 200 unit-tiles x 2 dirs; 128 threads.
// Loops t = 0..511 internally with a software grid barrier between steps.
// Gate tile per block: [32 batch] x [16 rows] (4 gates x 4 units), K = 800.
#define NBLK_LSTM 400u
__global__ void __launch_bounds__(128, 4)
k_lstm(const float* __restrict__ Whh_f, const float* __restrict__ Whh_b, int layer)
{
    int dir = blockIdx.x & 1;
    int u0  = (blockIdx.x >> 1) * 4;

    const float* Whh  = dir ? Whh_b : Whh_f;
    const float* Gbase= g_G[layer*2 + dir];
    float*       cst  = g_cs[layer][dir];
    float*       hout = layer ? g_h2 : g_h1;
    float*       hbuf0 = g_hs[layer][dir][0];
    float*       hbuf1 = g_hs[layer][dir][1];

    __shared__ float sh[32][34];   // [k][batch]
    __shared__ float sw[32][18];   // [k][row]
    __shared__ float sg[32][17];   // [batch][row]

    int tid  = threadIdx.x;
    int lane = tid & 31;
    int warp = tid >> 5;
    // broadcast-friendly mapping: within a warp, 8 batch-pairs x 4 row-pairs
    int b2 = (lane & 7) + ((warp & 1) << 3);         // 0..15
    int r2 = ((lane >> 3) & 3) + ((warp >> 1) << 2); // 0..7
    int bb0 = 2 * b2;
    int rr0 = 2 * r2;

    // loader indices
    int lb  = tid & 31;       // h-loader: batch
    int lkq = tid >> 5;       // h-loader: 8-k group (0..3)
    int wrr = tid & 15;       // w-loader: row 0..15
    int wkq = tid >> 4;       // w-loader: 4-k group (0..7)
    int wj  = (wrr >> 2) * HDIM + u0 + (wrr & 3);    // global gate row

    // cell-update indices
    int ub = tid & 31;
    int uu = tid >> 5;        // 0..3
    int uidx = ub * HDIM + u0 + uu;

    // gate column indices for the accumulate stage
    int q  = rr0 >> 2;
    int jA = q * HDIM + u0 + (rr0 & 3);

    for (int t = 0; t < LSEQ; t++) {
        int tt = dir ? (LSEQ - 1 - t) : t;
        const float* hin = (t & 1) ? hbuf1 : hbuf0;
        float*       hnx = (t & 1) ? hbuf0 : hbuf1;
        const float* G   = Gbase + (size_t)tt * (BATCH * G4);

        float a00 = 0.f, a01 = 0.f, a10 = 0.f, a11 = 0.f;

        for (int k0 = 0; k0 < HDIM; k0 += 32) {
            const float* hrow = hin + lb * HDIM + k0 + lkq * 8;
            float4 v0 = *(const float4*)hrow;
            float4 v1 = *(const float4*)(hrow + 4);
            int kb = lkq * 8;
            sh[kb+0][lb] = v0.x; sh[kb+1][lb] = v0.y; sh[kb+2][lb] = v0.z; sh[kb+3][lb] = v0.w;
            sh[kb+4][lb] = v1.x; sh[kb+5][lb] = v1.y; sh[kb+6][lb] = v1.z; sh[kb+7][lb] = v1.w;

            float4 w4 = *(const float4*)(Whh + (size_t)wj * HDIM + k0 + wkq * 4);
            int kw = wkq * 4;
            sw[kw+0][wrr] = w4.x; sw[kw+1][wrr] = w4.y; sw[kw+2][wrr] = w4.z; sw[kw+3][wrr] = w4.w;
            __syncthreads();

            #pragma unroll
            for (int k = 0; k < 32; k++) {
                float2 hv = *(const float2*)&sh[k][bb0];
                float2 wv = *(const float2*)&sw[k][rr0];
                a00 = fmaf(hv.x, wv.x, a00);
                a01 = fmaf(hv.x, wv.y, a01);
                a10 = fmaf(hv.y, wv.x, a10);
                a11 = fmaf(hv.y, wv.y, a11);
            }
            __syncthreads();
        }

        // add precomputed input gates + biases, stage into sg[batch][row]
        sg[bb0  ][rr0  ] = a00 + G[(size_t)bb0     * G4 + jA];
        sg[bb0  ][rr0+1] = a01 + G[(size_t)bb0     * G4 + jA + 1];
        sg[bb0+1][rr0  ] = a10 + G[(size_t)(bb0+1) * G4 + jA];
        sg[bb0+1][rr0+1] = a11 + G[(size_t)(bb0+1) * G4 + jA + 1];
        __syncthreads();

        // cell update: 128 threads = 32 batch x 4 units
        {
            float gi = sg[ub][0*4 + uu];
            float gf = sg[ub][1*4 + uu];
            float gg = sg[ub][2*4 + uu];
            float go = sg[ub][3*4 + uu];
            float c  = cst[uidx];
            float si = 1.f / (1.f + expf(-gi));
            float sf = 1.f / (1.f + expf(-gf));
            float so = 1.f / (1.f + expf(-go));
            float cn = sf * c + si * tanhf(gg);
            float hn = so * tanhf(cn);
            cst[uidx] = cn;
            hnx[uidx] = hn;
            hout[((size_t)tt * BATCH + ub) * H2 + dir * HDIM + u0 + uu] = hn;
        }

        grid_sync(NBLK_LSTM);
    }
}

// ---------------- linear + softmax + angle mixture -----------------------------
// one warp per (t,b)
__global__ void k_angles(const float* __restrict__ Wlin,
                         const float* __restrict__ blin,
                         const float* __restrict__ alpha)
{
    int w = blockIdx.x * (blockDim.x >> 5) + (threadIdx.x >> 5);
    int lane = threadIdx.x & 31;
    const float* hv = g_h2 + (size_t)w * H2;

    float acc[ASZ];
    #pragma unroll
    for (int j = 0; j < ASZ; j++) acc[j] = 0.f;

    for (int kk = 0; kk < H2 / 32; kk++) {
        float h = hv[lane + kk * 32];
        #pragma unroll
        for (int j = 0; j < ASZ; j++)
            acc[j] = fmaf(h, Wlin[(size_t)j * H2 + lane + kk * 32], acc[j]);
    }
    #pragma unroll
    for (int j = 0; j < ASZ; j++) {
        float v = acc[j];
        #pragma unroll
        for (int s = 16; s; s >>= 1) v += __shfl_xor_sync(0xffffffffu, v, s);
        acc[j] = v + blin[j];
    }
    // softmax over 20 (all lanes hold identical values)
    float mx = acc[0];
    #pragma unroll
    for (int j = 1; j < ASZ; j++) mx = fmaxf(mx, acc[j]);
    float sum = 0.f;
    #pragma unroll
    for (int j = 0; j < ASZ; j++) { acc[j] = expf(acc[j] - mx); sum += acc[j]; }
    float inv = 1.f / sum;

    if (lane < 3) {
        float sm = 0.f, cm = 0.f;
        #pragma unroll
        for (int j = 0; j < ASZ; j++) {
            float p = acc[j] * inv;
            float a = alpha[j * 3 + lane];
            sm = fmaf(p, sinf(a), sm);
            cm = fmaf(p, cosf(a), cm);
        }
        float ang = atan2f(sm, cm);
        int t = w / BATCH, b = w % BATCH;
        g_phi[(t * 3 + lane) * BATCH + b] = ang;
    }
}

// ---------------- NeRF: sequential coordinate extension ------------------------
__global__ void k_nerf(float* __restrict__ out)
{
    int b = threadIdx.x;   // 32 threads, one chain each
    const float PI_F = 3.14159265358979323846f;
    const float bl[3] = {1.458f, 1.525f, 1.329f};
    const float ba[3] = {2.124f, 1.941f, 2.028f};
    float ct[3], st[3];
    #pragma unroll
    for (int r = 0; r < 3; r++) { float th = PI_F - ba[r]; ct[r] = cosf(th); st[r] = sinf(th); }

    float ax = 0.f, ay = 0.f, az = 0.f;
    float bx = 1.458f, by = 0.f, bz = 0.f;
    float th0 = PI_F - 2.124f;
    float cx = bx + 1.525f * cosf(th0);
    float cy = 1.525f * sinf(th0);
    float cz = 0.f;

    int r = 0;
    #pragma unroll 1
    for (int i = 0; i < L3; i++) {
        float phi = g_phi[i * BATCH + b];
        // bc = normalize(C - B)
        float vx = cx - bx, vy = cy - by, vz = cz - bz;
        float n1 = sqrtf(vx*vx + vy*vy + vz*vz);
        float s1 = 1.f / (n1 + 1e-8f);
        float bcx = vx * s1, bcy = vy * s1, bcz = vz * s1;
        // n = normalize(cross(B - A, bc))
        float ux = bx - ax, uy = by - ay, uz = bz - az;
        float nx = uy * bcz - uz * bcy;
        float ny = uz * bcx - ux * bcz;
        float nz = ux * bcy - uy * bcx;
        float n2 = sqrtf(nx*nx + ny*ny + nz*nz);
        float s2 = 1.f / (n2 + 1e-8f);
        nx *= s2; ny *= s2; nz *= s2;
        // m = cross(n, bc)
        float mx = ny * bcz - nz * bcy;
        float my = nz * bcx - nx * bcz;
        float mz = nx * bcy - ny * bcx;

        float sp, cp;
        sincosf(phi, &sp, &cp);
        float d = bl[r];
        float c_t = ct[r], s_t = st[r];

        float wx = cx + d * (c_t * bcx + s_t * (cp * mx + sp * nx));
        float wy = cy + d * (c_t * bcy + s_t * (cp * my + sp * ny));
        float wz = cz + d * (c_t * bcz + s_t * (cp * mz + sp * nz));

        size_t o = ((size_t)i * BATCH + b) * 3;
        out[o + 0] = wx; out[o + 1] = wy; out[o + 2] = wz;

        ax = bx; ay = by; az = bz;
        bx = cx; by = cy; bz = cz;
        cx = wx; cy = wy; cz = wz;
        r = (r == 2) ? 0 : (r + 1);
    }
}

// ---------------- launch --------------------------------------------------------
extern "C" void kernel_launch(void* const* d_in, const int* in_sizes, int n_in,
                              void* d_out, int out_size)
{
    const float* x     = (const float*)d_in[0];
    const float* Wih0f = (const float*)d_in[1];
    const float* Whh0f = (const float*)d_in[2];
    const float* bih0f = (const float*)d_in[3];
    const float* bhh0f = (const float*)d_in[4];
    const float* Wih0b = (const float*)d_in[5];
    const float* Whh0b = (const float*)d_in[6];
    const float* bih0b = (const float*)d_in[7];
    const float* bhh0b = (const float*)d_in[8];
    const float* Wih1f = (const float*)d_in[9];
    const float* Whh1f = (const float*)d_in[10];
    const float* bih1f = (const float*)d_in[11];
    const float* bhh1f = (const float*)d_in[12];
    const float* Wih1b = (const float*)d_in[13];
    const float* Whh1b = (const float*)d_in[14];
    const float* bih1b = (const float*)d_in[15];
    const float* bhh1b = (const float*)d_in[16];
    const float* W_lin = (const float*)d_in[17];
    const float* b_lin = (const float*)d_in[18];
    const float* alpha = (const float*)d_in[19];

    // zero LSTM states (graph replays mutate them)
    k_init<<<800, 256>>>();

    // layer-0 input projections (both directions)
    k_proj0<<<dim3(LSEQ * BATCH, 2), 256>>>(x, Wih0f, bih0f, bhh0f, Wih0b, bih0b, bhh0b);

    // layer-0 recurrence (persistent, 1 launch)
    k_lstm<<<NBLK_LSTM, 128>>>(Whh0f, Whh0b, 0);

    // layer-1 input projections (big GEMM, both directions)
    k_proj1<<<dim3(G4 / BN, (LSEQ * BATCH) / BM, 2), 256>>>(Wih1f, bih1f, bhh1f,
                                                            Wih1b, bih1b, bhh1b);

    // layer-1 recurrence (persistent, 1 launch)
    k_lstm<<<NBLK_LSTM, 128>>>(Whh1f, Whh1b, 1);

    // linear + softmax + angle mixture
    k_angles<<<(LSEQ * BATCH) / 8, 256>>>(W_lin, b_lin, alpha);

    // NeRF chain extension
    k_nerf<<<1, 32>>>((float*)d_out);
}

// round 5
// speedup vs baseline: 1.2113x; 1.2113x over previous
#include <cuda_runtime.h>
#include <cuda_bf16.h>
#include <math.h>

#define LSEQ 512
#define BATCH 32
#define DIN 42
#define HDIM 800
#define G4 3200          // 4*HDIM
#define H2 1600          // 2*HDIM
#define ASZ 20
#define L3 (3*LSEQ)

// ---------------- static device scratch (no allocations allowed) ----------------
__device__ float g_G[4][LSEQ*BATCH*G4];
__device__ float g_h1[LSEQ*BATCH*H2];
__device__ float g_h2[LSEQ*BATCH*H2];
__device__ float g_hs[2][2][2][BATCH*HDIM];   // [layer][dir][parity][b*H+u]
__device__ float g_cs[2][2][BATCH*HDIM];      // [layer][dir][b*H+u]
__device__ float g_phi[L3*BATCH];             // [3L][B]

// software grid barrier
__device__ unsigned g_barc = 0;
__device__ unsigned g_barp = 0;

__device__ __forceinline__ void grid_sync(unsigned nblocks)
{
    __syncthreads();
    if (threadIdx.x == 0) {
        __threadfence();
        unsigned gen = *((volatile unsigned*)&g_barp);
        if (atomicAdd(&g_barc, 1u) == nblocks - 1u) {
            g_barc = 0;
            __threadfence();
            atomicAdd(&g_barp, 1u);
        } else {
            while (*((volatile unsigned*)&g_barp) == gen) { }
        }
        __threadfence();
    }
    __syncthreads();
}

// ---------------- init ----------------------------------------------------------
__global__ void k_init()
{
    int i = blockIdx.x * blockDim.x + threadIdx.x;
    if (i < 2*2*2*BATCH*HDIM) ((float*)g_hs)[i] = 0.f;
    if (i < 2*2*BATCH*HDIM)   ((float*)g_cs)[i] = 0.f;
}

// ---------------- layer0 input projection --------------------------------------
__global__ void k_proj0(const float* __restrict__ x,
                        const float* __restrict__ Wf, const float* __restrict__ bif, const float* __restrict__ bhf,
                        const float* __restrict__ Wb, const float* __restrict__ bib, const float* __restrict__ bhb)
{
    int tb  = blockIdx.x;
    int dir = blockIdx.y;
    const float* W  = dir ? Wb : Wf;
    const float* b1 = dir ? bib : bif;
    const float* b2 = dir ? bhb : bhf;
    float* G = g_G[dir] + (size_t)tb * G4;

    __shared__ float sx[DIN];
    if (threadIdx.x < DIN) sx[threadIdx.x] = x[(size_t)tb*DIN + threadIdx.x];
    __syncthreads();

    for (int j = threadIdx.x; j < G4; j += blockDim.x) {
        const float* wr = W + (size_t)j * DIN;
        float acc = b1[j] + b2[j];
        #pragma unroll
        for (int k = 0; k < DIN; k++) acc = fmaf(wr[k], sx[k], acc);
        G[j] = acc;
    }
}

// ---------------- tf32 helpers --------------------------------------------------
__device__ __forceinline__ unsigned f2tf32(float x)
{
    unsigned r;
    asm("cvt.rna.tf32.f32 %0, %1;" : "=r"(r) : "f"(x));
    return r;
}

__device__ __forceinline__ void mma_tf32(float* d, unsigned a0, unsigned a1, unsigned a2, unsigned a3,
                                         unsigned b0, unsigned b1)
{
    asm volatile("mma.sync.aligned.m16n8k8.row.col.f32.tf32.tf32.f32 "
                 "{%0,%1,%2,%3}, {%4,%5,%6,%7}, {%8,%9}, {%0,%1,%2,%3};"
                 : "+f"(d[0]), "+f"(d[1]), "+f"(d[2]), "+f"(d[3])
                 : "r"(a0), "r"(a1), "r"(a2), "r"(a3), "r"(b0), "r"(b1));
}

// ---------------- layer1 input projection: tf32 tensor-core GEMM ----------------
// C[16384,3200] = A[16384,1600] @ W[3200,1600]^T + bias, 2-term tf32 split.
// Block tile 128x128, BK=16, 256 threads (8 warps, warp tile 32x64).
#define PSTR 20
__global__ void __launch_bounds__(256)
k_proj1(const float* __restrict__ Wf, const float* __restrict__ bif, const float* __restrict__ bhf,
        const float* __restrict__ Wb, const float* __restrict__ bib, const float* __restrict__ bhb)
{
    int dir = blockIdx.z;
    const float* Bm = dir ? Wb : Wf;
    const float* b1 = dir ? bib : bif;
    const float* b2 = dir ? bhb : bhf;
    const float* A  = g_h1;
    float* C = g_G[2 + dir];

    int m0 = blockIdx.y * 128;
    int n0 = blockIdx.x * 128;

    __shared__ float Ah[128*PSTR], Al[128*PSTR], Bh[128*PSTR], Bl[128*PSTR];

    int tid  = threadIdx.x;
    int warp = tid >> 5;
    int lane = tid & 31;
    int g    = lane >> 2;     // 0..7
    int tig  = lane & 3;      // 0..3

    int wm = (warp & 3) * 32;
    int wn = (warp >> 2) * 64;

    // loader: row = tid>>1 (0..127), kq = (tid&1)*8
    int lrow = tid >> 1;
    int lkq  = (tid & 1) * 8;

    float acc[2][8][4];
    #pragma unroll
    for (int i = 0; i < 2; i++)
        #pragma unroll
        for (int j = 0; j < 8; j++)
            #pragma unroll
            for (int q = 0; q < 4; q++) acc[i][j][q] = 0.f;

    // prefetch first tile
    float4 av0 = *(const float4*)(A  + (size_t)(m0 + lrow)*H2 + 0 + lkq);
    float4 av1 = *(const float4*)(A  + (size_t)(m0 + lrow)*H2 + 0 + lkq + 4);
    float4 bv0 = *(const float4*)(Bm + (size_t)(n0 + lrow)*H2 + 0 + lkq);
    float4 bv1 = *(const float4*)(Bm + (size_t)(n0 + lrow)*H2 + 0 + lkq + 4);

    for (int it = 0; it < 100; it++) {
        // stage current regs into smem with hi/lo split
        {
            float va[8] = {av0.x, av0.y, av0.z, av0.w, av1.x, av1.y, av1.z, av1.w};
            float vb[8] = {bv0.x, bv0.y, bv0.z, bv0.w, bv1.x, bv1.y, bv1.z, bv1.w};
            #pragma unroll
            for (int j = 0; j < 8; j++) {
                float ahi = __uint_as_float(f2tf32(va[j]));
                float alo = __uint_as_float(f2tf32(va[j] - ahi));
                Ah[lrow*PSTR + lkq + j] = ahi;
                Al[lrow*PSTR + lkq + j] = alo;
                float bhi = __uint_as_float(f2tf32(vb[j]));
                float blo = __uint_as_float(f2tf32(vb[j] - bhi));
                Bh[lrow*PSTR + lkq + j] = bhi;
                Bl[lrow*PSTR + lkq + j] = blo;
            }
        }
        __syncthreads();

        if (it < 99) {
            int k0 = (it + 1) * 16;
            av0 = *(const float4*)(A  + (size_t)(m0 + lrow)*H2 + k0 + lkq);
            av1 = *(const float4*)(A  + (size_t)(m0 + lrow)*H2 + k0 + lkq + 4);
            bv0 = *(const float4*)(Bm + (size_t)(n0 + lrow)*H2 + k0 + lkq);
            bv1 = *(const float4*)(Bm + (size_t)(n0 + lrow)*H2 + k0 + lkq + 4);
        }

        #pragma unroll
        for (int kk = 0; kk < 16; kk += 8) {
            unsigned ah[2][4], al[2][4];
            #pragma unroll
            for (int mf = 0; mf < 2; mf++) {
                int r0 = wm + mf*16 + g;
                int r1 = r0 + 8;
                int c0 = kk + tig, c1 = kk + tig + 4;
                ah[mf][0] = __float_as_uint(Ah[r0*PSTR + c0]);
                ah[mf][1] = __float_as_uint(Ah[r1*PSTR + c0]);
                ah[mf][2] = __float_as_uint(Ah[r0*PSTR + c1]);
                ah[mf][3] = __float_as_uint(Ah[r1*PSTR + c1]);
                al[mf][0] = __float_as_uint(Al[r0*PSTR + c0]);
                al[mf][1] = __float_as_uint(Al[r1*PSTR + c0]);
                al[mf][2] = __float_as_uint(Al[r0*PSTR + c1]);
                al[mf][3] = __float_as_uint(Al[r1*PSTR + c1]);
            }
            #pragma unroll
            for (int nf = 0; nf < 8; nf++) {
                int n = wn + nf*8 + g;
                unsigned bh0 = __float_as_uint(Bh[n*PSTR + kk + tig]);
                unsigned bh1 = __float_as_uint(Bh[n*PSTR + kk + tig + 4]);
                unsigned bl0 = __float_as_uint(Bl[n*PSTR + kk + tig]);
                unsigned bl1 = __float_as_uint(Bl[n*PSTR + kk + tig + 4]);
                #pragma unroll
                for (int mf = 0; mf < 2; mf++) {
                    mma_tf32(acc[mf][nf], ah[mf][0], ah[mf][1], ah[mf][2], ah[mf][3], bh0, bh1);
                    mma_tf32(acc[mf][nf], ah[mf][0], ah[mf][1], ah[mf][2], ah[mf][3], bl0, bl1);
                    mma_tf32(acc[mf][nf], al[mf][0], al[mf][1], al[mf][2], al[mf][3], bh0, bh1);
                }
            }
        }
        __syncthreads();
    }

    // epilogue: acc -> C with bias
    #pragma unroll
    for (int mf = 0; mf < 2; mf++) {
        int r0 = m0 + wm + mf*16 + g;
        #pragma unroll
        for (int nf = 0; nf < 8; nf++) {
            int col = n0 + wn + nf*8 + 2*tig;
            float bb0 = b1[col]   + b2[col];
            float bb1 = b1[col+1] + b2[col+1];
            float2 v0 = make_float2(acc[mf][nf][0] + bb0, acc[mf][nf][1] + bb1);
            float2 v1 = make_float2(acc[mf][nf][2] + bb0, acc[mf][nf][3] + bb1);
            *(float2*)(C + (size_t)r0*G4 + col)     = v0;
            *(float2*)(C + (size_t)(r0+8)*G4 + col) = v1;
        }
    }
}

// ---------------- persistent bi-LSTM recurrence, weights smem-resident ----------
// grid 400 = 200 unit-tiles x 2 dirs, 128 threads, dynamic smem 68480 B.
// Weights (16 rows x 800) loaded to smem ONCE, reused for all 512 steps.
#define NBLK_LSTM 400u
#define WSTR 18
#define SHSTR 34
#define LSTM_SMEM ((800*WSTR + 2*32*SHSTR + 32*17) * 4)
__global__ void __launch_bounds__(128, 3)
k_lstm(const float* __restrict__ Whh_f, const float* __restrict__ Whh_b, int layer)
{
    extern __shared__ float dsm[];
    float* ws  = dsm;                  // [800][18] weights
    float* shb = dsm + 800*WSTR;       // [2][32][34] h double buffer
    float* sgm = shb + 2*32*SHSTR;     // [32][17] gate staging

    int dir = blockIdx.x & 1;
    int u0  = (blockIdx.x >> 1) * 4;

    const float* Whh  = dir ? Whh_b : Whh_f;
    const float* Gbase= g_G[layer*2 + dir];
    float*       cst  = g_cs[layer][dir];
    float*       hout = layer ? g_h2 : g_h1;
    float*       hbuf0 = g_hs[layer][dir][0];
    float*       hbuf1 = g_hs[layer][dir][1];

    int tid  = threadIdx.x;
    int lane = tid & 31;
    int warp = tid >> 5;
    int b2i = (lane & 7) + ((warp & 1) << 3);
    int r2i = ((lane >> 3) & 3) + ((warp >> 1) << 2);
    int bb0 = 2 * b2i;
    int rr0 = 2 * r2i;

    // h loader
    int lb  = tid & 31;
    int lkq = tid >> 5;           // 0..3 -> 8 floats each
    // weight loader
    int wrr = tid & 15;
    int wkq = tid >> 4;           // 0..7 -> 4 floats each
    int wj  = (wrr >> 2) * HDIM + u0 + (wrr & 3);

    // cell update
    int ub = tid & 31;
    int uu = tid >> 5;
    int uidx = ub * HDIM + u0 + uu;

    int jA = (rr0 >> 2) * HDIM + u0 + (rr0 & 3);

    // ---- load weights into smem once ----
    for (int k0 = 0; k0 < HDIM; k0 += 32) {
        float4 w4 = *(const float4*)(Whh + (size_t)wj * HDIM + k0 + wkq * 4);
        int kw = k0 + wkq * 4;
        ws[(kw+0)*WSTR + wrr] = w4.x;
        ws[(kw+1)*WSTR + wrr] = w4.y;
        ws[(kw+2)*WSTR + wrr] = w4.z;
        ws[(kw+3)*WSTR + wrr] = w4.w;
    }
    __syncthreads();

    for (int t = 0; t < LSEQ; t++) {
        int tt = dir ? (LSEQ - 1 - t) : t;
        const float* hin = (t & 1) ? hbuf1 : hbuf0;
        float*       hnx = (t & 1) ? hbuf0 : hbuf1;
        const float* G   = Gbase + (size_t)tt * (BATCH * G4);

        // prefetch input-gate values (4 per thread)
        float gp00 = G[(size_t)bb0     * G4 + jA];
        float gp01 = G[(size_t)bb0     * G4 + jA + 1];
        float gp10 = G[(size_t)(bb0+1) * G4 + jA];
        float gp11 = G[(size_t)(bb0+1) * G4 + jA + 1];

        float a00 = 0.f, a01 = 0.f, a10 = 0.f, a11 = 0.f;

        // prologue: load h tile 0 into buffer 0
        {
            const float* hrow = hin + lb * HDIM + lkq * 8;
            float4 v0 = *(const float4*)hrow;
            float4 v1 = *(const float4*)(hrow + 4);
            int kb = lkq * 8;
            float* sb = shb;  // buffer 0
            sb[(kb+0)*SHSTR + lb] = v0.x; sb[(kb+1)*SHSTR + lb] = v0.y;
            sb[(kb+2)*SHSTR + lb] = v0.z; sb[(kb+3)*SHSTR + lb] = v0.w;
            sb[(kb+4)*SHSTR + lb] = v1.x; sb[(kb+5)*SHSTR + lb] = v1.y;
            sb[(kb+6)*SHSTR + lb] = v1.z; sb[(kb+7)*SHSTR + lb] = v1.w;
        }
        __syncthreads();

        for (int kt = 0; kt < 25; kt++) {
            int cur = kt & 1;
            float4 v0, v1;
            if (kt < 24) {
                const float* hrow = hin + lb * HDIM + (kt+1)*32 + lkq * 8;
                v0 = *(const float4*)hrow;
                v1 = *(const float4*)(hrow + 4);
            }

            const float* shp = shb + cur * (32*SHSTR);
            const float* wsp = ws + kt * 32 * WSTR;
            #pragma unroll
            for (int k = 0; k < 32; k++) {
                float2 hv = *(const float2*)(shp + k*SHSTR + bb0);
                float2 wv = *(const float2*)(wsp + k*WSTR + rr0);
                a00 = fmaf(hv.x, wv.x, a00);
                a01 = fmaf(hv.x, wv.y, a01);
                a10 = fmaf(hv.y, wv.x, a10);
                a11 = fmaf(hv.y, wv.y, a11);
            }

            if (kt < 24) {
                float* sb = shb + (1 - cur) * (32*SHSTR);
                int kb = lkq * 8;
                sb[(kb+0)*SHSTR + lb] = v0.x; sb[(kb+1)*SHSTR + lb] = v0.y;
                sb[(kb+2)*SHSTR + lb] = v0.z; sb[(kb+3)*SHSTR + lb] = v0.w;
                sb[(kb+4)*SHSTR + lb] = v1.x; sb[(kb+5)*SHSTR + lb] = v1.y;
                sb[(kb+6)*SHSTR + lb] = v1.z; sb[(kb+7)*SHSTR + lb] = v1.w;
                __syncthreads();
            }
        }

        // stage gates into sgm[batch][row]
        sgm[bb0*17     + rr0    ] = a00 + gp00;
        sgm[bb0*17     + rr0 + 1] = a01 + gp01;
        sgm[(bb0+1)*17 + rr0    ] = a10 + gp10;
        sgm[(bb0+1)*17 + rr0 + 1] = a11 + gp11;
        __syncthreads();

        // cell update: 32 batch x 4 units
        {
            float gi = sgm[ub*17 + 0*4 + uu];
            float gf = sgm[ub*17 + 1*4 + uu];
            float gg = sgm[ub*17 + 2*4 + uu];
            float go = sgm[ub*17 + 3*4 + uu];
            float c  = cst[uidx];
            float si = 1.f / (1.f + expf(-gi));
            float sf = 1.f / (1.f + expf(-gf));
            float so = 1.f / (1.f + expf(-go));
            float cn = sf * c + si * tanhf(gg);
            float hn = so * tanhf(cn);
            cst[uidx] = cn;
            hnx[uidx] = hn;
            hout[((size_t)tt * BATCH + ub) * H2 + dir * HDIM + u0 + uu] = hn;
        }

        grid_sync(NBLK_LSTM);
    }
}

// ---------------- linear + softmax + angle mixture ------------------------------
__global__ void k_angles(const float* __restrict__ Wlin,
                         const float* __restrict__ blin,
                         const float* __restrict__ alpha)
{
    int w = blockIdx.x * (blockDim.x >> 5) + (threadIdx.x >> 5);
    int lane = threadIdx.x & 31;
    const float* hv = g_h2 + (size_t)w * H2;

    float acc[ASZ];
    #pragma unroll
    for (int j = 0; j < ASZ; j++) acc[j] = 0.f;

    for (int kk = 0; kk < H2 / 32; kk++) {
        float h = hv[lane + kk * 32];
        #pragma unroll
        for (int j = 0; j < ASZ; j++)
            acc[j] = fmaf(h, Wlin[(size_t)j * H2 + lane + kk * 32], acc[j]);
    }
    #pragma unroll
    for (int j = 0; j < ASZ; j++) {
        float v = acc[j];
        #pragma unroll
        for (int s = 16; s; s >>= 1) v += __shfl_xor_sync(0xffffffffu, v, s);
        acc[j] = v + blin[j];
    }
    float mx = acc[0];
    #pragma unroll
    for (int j = 1; j < ASZ; j++) mx = fmaxf(mx, acc[j]);
    float sum = 0.f;
    #pragma unroll
    for (int j = 0; j < ASZ; j++) { acc[j] = expf(acc[j] - mx); sum += acc[j]; }
    float inv = 1.f / sum;

    if (lane < 3) {
        float sm = 0.f, cm = 0.f;
        #pragma unroll
        for (int j = 0; j < ASZ; j++) {
            float p = acc[j] * inv;
            float a = alpha[j * 3 + lane];
            sm = fmaf(p, sinf(a), sm);
            cm = fmaf(p, cosf(a), cm);
        }
        float ang = atan2f(sm, cm);
        int t = w / BATCH, b = w % BATCH;
        g_phi[(t * 3 + lane) * BATCH + b] = ang;
    }
}

// ---------------- NeRF ----------------------------------------------------------
__global__ void k_nerf(float* __restrict__ out)
{
    int b = threadIdx.x;
    const float PI_F = 3.14159265358979323846f;
    const float bl[3] = {1.458f, 1.525f, 1.329f};
    const float ba[3] = {2.124f, 1.941f, 2.028f};
    float ct[3], st[3];
    #pragma unroll
    for (int r = 0; r < 3; r++) { float th = PI_F - ba[r]; ct[r] = cosf(th); st[r] = sinf(th); }

    float ax = 0.f, ay = 0.f, az = 0.f;
    float bx = 1.458f, by = 0.f, bz = 0.f;
    float th0 = PI_F - 2.124f;
    float cx = bx + 1.525f * cosf(th0);
    float cy = 1.525f * sinf(th0);
    float cz = 0.f;

    int r = 0;
    #pragma unroll 1
    for (int i = 0; i < L3; i++) {
        float phi = g_phi[i * BATCH + b];
        float vx = cx - bx, vy = cy - by, vz = cz - bz;
        float n1 = sqrtf(vx*vx + vy*vy + vz*vz);
        float s1 = 1.f / (n1 + 1e-8f);
        float bcx = vx * s1, bcy = vy * s1, bcz = vz * s1;
        float ux = bx - ax, uy = by - ay, uz = bz - az;
        float nx = uy * bcz - uz * bcy;
        float ny = uz * bcx - ux * bcz;
        float nz = ux * bcy - uy * bcx;
        float n2 = sqrtf(nx*nx + ny*ny + nz*nz);
        float s2 = 1.f / (n2 + 1e-8f);
        nx *= s2; ny *= s2; nz *= s2;
        float mx = ny * bcz - nz * bcy;
        float my = nz * bcx - nx * bcz;
        float mz = nx * bcy - ny * bcx;

        float sp, cp;
        sincosf(phi, &sp, &cp);
        float d = bl[r];
        float c_t = ct[r], s_t = st[r];

        float wx = cx + d * (c_t * bcx + s_t * (cp * mx + sp * nx));
        float wy = cy + d * (c_t * bcy + s_t * (cp * my + sp * ny));
        float wz = cz + d * (c_t * bcz + s_t * (cp * mz + sp * nz));

        size_t o = ((size_t)i * BATCH + b) * 3;
        out[o + 0] = wx; out[o + 1] = wy; out[o + 2] = wz;

        ax = bx; ay = by; az = bz;
        bx = cx; by = cy; bz = cz;
        cx = wx; cy = wy; cz = wz;
        r = (r == 2) ? 0 : (r + 1);
    }
}

// ---------------- launch --------------------------------------------------------
extern "C" void kernel_launch(void* const* d_in, const int* in_sizes, int n_in,
                              void* d_out, int out_size)
{
    const float* x     = (const float*)d_in[0];
    const float* Wih0f = (const float*)d_in[1];
    const float* Whh0f = (const float*)d_in[2];
    const float* bih0f = (const float*)d_in[3];
    const float* bhh0f = (const float*)d_in[4];
    const float* Wih0b = (const float*)d_in[5];
    const float* Whh0b = (const float*)d_in[6];
    const float* bih0b = (const float*)d_in[7];
    const float* bhh0b = (const float*)d_in[8];
    const float* Wih1f = (const float*)d_in[9];
    const float* Whh1f = (const float*)d_in[10];
    const float* bih1f = (const float*)d_in[11];
    const float* bhh1f = (const float*)d_in[12];
    const float* Wih1b = (const float*)d_in[13];
    const float* Whh1b = (const float*)d_in[14];
    const float* bih1b = (const float*)d_in[15];
    const float* bhh1b = (const float*)d_in[16];
    const float* W_lin = (const float*)d_in[17];
    const float* b_lin = (const float*)d_in[18];
    const float* alpha = (const float*)d_in[19];

    static int s_attr_done = 0;
    if (!s_attr_done) {
        cudaFuncSetAttribute(k_lstm, cudaFuncAttributeMaxDynamicSharedMemorySize, LSTM_SMEM);
        s_attr_done = 1;
    }

    k_init<<<800, 256>>>();

    k_proj0<<<dim3(LSEQ * BATCH, 2), 256>>>(x, Wih0f, bih0f, bhh0f, Wih0b, bih0b, bhh0b);

    k_lstm<<<NBLK_LSTM, 128, LSTM_SMEM>>>(Whh0f, Whh0b, 0);

    k_proj1<<<dim3(G4 / 128, (LSEQ * BATCH) / 128, 2), 256>>>(Wih1f, bih1f, bhh1f,
                                                              Wih1b, bih1b, bhh1b);

    k_lstm<<<NBLK_LSTM, 128, LSTM_SMEM>>>(Whh1f, Whh1b, 1);

    k_angles<<<(LSEQ * BATCH) / 8, 256>>>(W_lin, b_lin, alpha);

    k_nerf<<<1, 32>>>((float*)d_out);
}

// round 6
// speedup vs baseline: 1.2737x; 1.0515x over previous
#include <cuda_runtime.h>
#include <cuda_bf16.h>
#include <math.h>

#define LSEQ 512
#define BATCH 32
#define DIN 42
#define HDIM 800
#define G4 3200          // 4*HDIM
#define H2 1600          // 2*HDIM
#define ASZ 20
#define L3 (3*LSEQ)

// ---------------- static device scratch (no allocations allowed) ----------------
__device__ float g_G[4][LSEQ*BATCH*G4];
__device__ float g_h1[LSEQ*BATCH*H2];
__device__ float g_h2[LSEQ*BATCH*H2];
__device__ float g_hs[2][2][2][BATCH*HDIM];   // [layer][dir][parity][b*H+u]
__device__ float g_cs[2][2][BATCH*HDIM];      // [layer][dir][b*H+u]
__device__ float g_phi[L3*BATCH];             // [3L][B]
// split recurrence weights: [layer][dir][tile*16*800 + r*800 + k] as (hi,lo)
__device__ float2 g_Wsp[2][2][3200*HDIM];
// per-(layer,dir) monotonic barrier counters
__device__ unsigned g_ctr[2][2];

// ---------------- init (graph is replayed; must re-zero) ------------------------
__global__ void k_init()
{
    int i = blockIdx.x * blockDim.x + threadIdx.x;
    if (i < 2*2*2*BATCH*HDIM) ((float*)g_hs)[i] = 0.f;
    if (i < 2*2*BATCH*HDIM)   ((float*)g_cs)[i] = 0.f;
    if (i < 4)                ((unsigned*)g_ctr)[i] = 0u;
}

// ---------------- tf32 helpers --------------------------------------------------
__device__ __forceinline__ unsigned f2tf32(float x)
{
    unsigned r;
    asm("cvt.rna.tf32.f32 %0, %1;" : "=r"(r) : "f"(x));
    return r;
}

__device__ __forceinline__ void mma_tf32(float* d, unsigned a0, unsigned a1, unsigned a2, unsigned a3,
                                         unsigned b0, unsigned b1)
{
    asm volatile("mma.sync.aligned.m16n8k8.row.col.f32.tf32.tf32.f32 "
                 "{%0,%1,%2,%3}, {%4,%5,%6,%7}, {%8,%9}, {%0,%1,%2,%3};"
                 : "+f"(d[0]), "+f"(d[1]), "+f"(d[2]), "+f"(d[3])
                 : "r"(a0), "r"(a1), "r"(a2), "r"(a3), "r"(b0), "r"(b1));
}

// ---------------- split Whh into (hi,lo) tf32 pairs, mma-friendly layout --------
// dest row = tile*16 + r, r = 4*q + j  ->  src row = q*800 + tile*4 + j
__global__ void k_wsplit(const float* __restrict__ Wf, const float* __restrict__ Wb, int layer)
{
    int dir  = blockIdx.y;
    const float* W = dir ? Wb : Wf;
    int row  = blockIdx.x;          // 0..3199
    int tile = row >> 4;
    int r    = row & 15;
    int q    = r >> 2, j = r & 3;
    const float* src = W + (size_t)(q*HDIM + tile*4 + j) * HDIM;
    float2* dst = g_Wsp[layer][dir] + (size_t)row * HDIM;
    for (int k = threadIdx.x; k < HDIM; k += blockDim.x) {
        float v  = src[k];
        float hi = __uint_as_float(f2tf32(v));
        float lo = __uint_as_float(f2tf32(v - hi));
        dst[k] = make_float2(hi, lo);
    }
}

// ---------------- layer0 input projection --------------------------------------
__global__ void k_proj0(const float* __restrict__ x,
                        const float* __restrict__ Wf, const float* __restrict__ bif, const float* __restrict__ bhf,
                        const float* __restrict__ Wb, const float* __restrict__ bib, const float* __restrict__ bhb)
{
    int tb  = blockIdx.x;
    int dir = blockIdx.y;
    const float* W  = dir ? Wb : Wf;
    const float* b1 = dir ? bib : bif;
    const float* b2 = dir ? bhb : bhf;
    float* G = g_G[dir] + (size_t)tb * G4;

    __shared__ float sx[DIN];
    if (threadIdx.x < DIN) sx[threadIdx.x] = x[(size_t)tb*DIN + threadIdx.x];
    __syncthreads();

    for (int j = threadIdx.x; j < G4; j += blockDim.x) {
        const float* wr = W + (size_t)j * DIN;
        float acc = b1[j] + b2[j];
        #pragma unroll
        for (int k = 0; k < DIN; k++) acc = fmaf(wr[k], sx[k], acc);
        G[j] = acc;
    }
}

// ---------------- layer1 input projection: tf32 tensor-core GEMM ----------------
#define PSTR 20
__global__ void __launch_bounds__(256)
k_proj1(const float* __restrict__ Wf, const float* __restrict__ bif, const float* __restrict__ bhf,
        const float* __restrict__ Wb, const float* __restrict__ bib, const float* __restrict__ bhb)
{
    int dir = blockIdx.z;
    const float* Bm = dir ? Wb : Wf;
    const float* b1 = dir ? bib : bif;
    const float* b2 = dir ? bhb : bhf;
    const float* A  = g_h1;
    float* C = g_G[2 + dir];

    int m0 = blockIdx.y * 128;
    int n0 = blockIdx.x * 128;

    __shared__ float Ah[128*PSTR], Al[128*PSTR], Bh[128*PSTR], Bl[128*PSTR];

    int tid  = threadIdx.x;
    int warp = tid >> 5;
    int lane = tid & 31;
    int g    = lane >> 2;
    int tig  = lane & 3;

    int wm = (warp & 3) * 32;
    int wn = (warp >> 2) * 64;

    int lrow = tid >> 1;
    int lkq  = (tid & 1) * 8;

    float acc[2][8][4];
    #pragma unroll
    for (int i = 0; i < 2; i++)
        #pragma unroll
        for (int j = 0; j < 8; j++)
            #pragma unroll
            for (int q = 0; q < 4; q++) acc[i][j][q] = 0.f;

    float4 av0 = *(const float4*)(A  + (size_t)(m0 + lrow)*H2 + 0 + lkq);
    float4 av1 = *(const float4*)(A  + (size_t)(m0 + lrow)*H2 + 0 + lkq + 4);
    float4 bv0 = *(const float4*)(Bm + (size_t)(n0 + lrow)*H2 + 0 + lkq);
    float4 bv1 = *(const float4*)(Bm + (size_t)(n0 + lrow)*H2 + 0 + lkq + 4);

    for (int it = 0; it < 100; it++) {
        {
            float va[8] = {av0.x, av0.y, av0.z, av0.w, av1.x, av1.y, av1.z, av1.w};
            float vb[8] = {bv0.x, bv0.y, bv0.z, bv0.w, bv1.x, bv1.y, bv1.z, bv1.w};
            #pragma unroll
            for (int j = 0; j < 8; j++) {
                float ahi = __uint_as_float(f2tf32(va[j]));
                float alo = __uint_as_float(f2tf32(va[j] - ahi));
                Ah[lrow*PSTR + lkq + j] = ahi;
                Al[lrow*PSTR + lkq + j] = alo;
                float bhi = __uint_as_float(f2tf32(vb[j]));
                float blo = __uint_as_float(f2tf32(vb[j] - bhi));
                Bh[lrow*PSTR + lkq + j] = bhi;
                Bl[lrow*PSTR + lkq + j] = blo;
            }
        }
        __syncthreads();

        if (it < 99) {
            int k0 = (it + 1) * 16;
            av0 = *(const float4*)(A  + (size_t)(m0 + lrow)*H2 + k0 + lkq);
            av1 = *(const float4*)(A  + (size_t)(m0 + lrow)*H2 + k0 + lkq + 4);
            bv0 = *(const float4*)(Bm + (size_t)(n0 + lrow)*H2 + k0 + lkq);
            bv1 = *(const float4*)(Bm + (size_t)(n0 + lrow)*H2 + k0 + lkq + 4);
        }

        #pragma unroll
        for (int kk = 0; kk < 16; kk += 8) {
            unsigned ah[2][4], al[2][4];
            #pragma unroll
            for (int mf = 0; mf < 2; mf++) {
                int r0 = wm + mf*16 + g;
                int r1 = r0 + 8;
                int c0 = kk + tig, c1 = kk + tig + 4;
                ah[mf][0] = __float_as_uint(Ah[r0*PSTR + c0]);
                ah[mf][1] = __float_as_uint(Ah[r1*PSTR + c0]);
                ah[mf][2] = __float_as_uint(Ah[r0*PSTR + c1]);
                ah[mf][3] = __float_as_uint(Ah[r1*PSTR + c1]);
                al[mf][0] = __float_as_uint(Al[r0*PSTR + c0]);
                al[mf][1] = __float_as_uint(Al[r1*PSTR + c0]);
                al[mf][2] = __float_as_uint(Al[r0*PSTR + c1]);
                al[mf][3] = __float_as_uint(Al[r1*PSTR + c1]);
            }
            #pragma unroll
            for (int nf = 0; nf < 8; nf++) {
                int n = wn + nf*8 + g;
                unsigned bh0 = __float_as_uint(Bh[n*PSTR + kk + tig]);
                unsigned bh1 = __float_as_uint(Bh[n*PSTR + kk + tig + 4]);
                unsigned bl0 = __float_as_uint(Bl[n*PSTR + kk + tig]);
                unsigned bl1 = __float_as_uint(Bl[n*PSTR + kk + tig + 4]);
                #pragma unroll
                for (int mf = 0; mf < 2; mf++) {
                    mma_tf32(acc[mf][nf], ah[mf][0], ah[mf][1], ah[mf][2], ah[mf][3], bh0, bh1);
                    mma_tf32(acc[mf][nf], ah[mf][0], ah[mf][1], ah[mf][2], ah[mf][3], bl0, bl1);
                    mma_tf32(acc[mf][nf], al[mf][0], al[mf][1], al[mf][2], al[mf][3], bh0, bh1);
                }
            }
        }
        __syncthreads();
    }

    #pragma unroll
    for (int mf = 0; mf < 2; mf++) {
        int r0 = m0 + wm + mf*16 + g;
        #pragma unroll
        for (int nf = 0; nf < 8; nf++) {
            int col = n0 + wn + nf*8 + 2*tig;
            float bb0 = b1[col]   + b2[col];
            float bb1 = b1[col+1] + b2[col+1];
            float2 v0 = make_float2(acc[mf][nf][0] + bb0, acc[mf][nf][1] + bb1);
            float2 v1 = make_float2(acc[mf][nf][2] + bb0, acc[mf][nf][3] + bb1);
            *(float2*)(C + (size_t)r0*G4 + col)     = v0;
            *(float2*)(C + (size_t)(r0+8)*G4 + col) = v1;
        }
    }
}

// ---------------- persistent bi-LSTM recurrence on tensor cores -----------------
// 400 blocks = 200 unit-tiles x 2 dirs, 128 threads (4 warps, K-split 200 each).
// Per block: gates[32 batch x 16 rows] = h[32x800] @ Wtile[16x800]^T via tf32 mma.
#define CH  160            // k-chunk staged in smem
#define AST 164            // smem stride (conflict-free: 164 mod 32 = 4)
#define LSTM_SMEM2 ((2*32*AST + 4*32*17) * 4)
__global__ void __launch_bounds__(128, 3)
k_lstm_mma(int layer)
{
    extern __shared__ float dsm[];
    float* Ah   = dsm;                      // [32][164] h hi
    float* Al   = dsm + 32*AST;             // [32][164] h lo
    float* sred = dsm + 2*32*AST;           // [4][32][17] partial gates

    int dir  = blockIdx.x & 1;
    int tile = blockIdx.x >> 1;
    int u0   = tile * 4;

    const float2* Wt   = g_Wsp[layer][dir] + (size_t)tile * 16 * HDIM;
    const float* Gbase = g_G[layer*2 + dir];
    float* cst  = g_cs[layer][dir];
    float* hout = layer ? g_h2 : g_h1;
    float* hb0  = g_hs[layer][dir][0];
    float* hb1  = g_hs[layer][dir][1];
    unsigned* ctr = &g_ctr[layer][dir];

    int tid  = threadIdx.x;
    int lane = tid & 31;
    int w    = tid >> 5;          // warp 0..3 = K-slice
    int g    = lane >> 2;         // 0..7
    int tig  = lane & 3;          // 0..3

    // staging ids: 128 threads = 32 batch x 4 k-quarters(40)
    int sb = tid & 31;
    int sq = tid >> 5;
    // cell-update ids
    int ub = tid & 31;
    int uu = tid >> 5;            // 0..3 unit
    int uidx = ub * HDIM + u0 + uu;

    for (int t = 0; t < LSEQ; t++) {
        int tt = dir ? (LSEQ - 1 - t) : t;
        const float* hin = (t & 1) ? hb1 : hb0;
        float*       hnx = (t & 1) ? hb0 : hb1;
        const float* G   = Gbase + (size_t)tt * (BATCH * G4);

        // prefetch this thread's 4 input-gate values
        const float* gp = G + (size_t)ub * G4 + u0 + uu;
        float gin0 = gp[0*HDIM], gin1 = gp[1*HDIM], gin2 = gp[2*HDIM], gin3 = gp[3*HDIM];

        float acc[2][2][4];
        #pragma unroll
        for (int mf = 0; mf < 2; mf++)
            #pragma unroll
            for (int nf = 0; nf < 2; nf++)
                #pragma unroll
                for (int q = 0; q < 4; q++) acc[mf][nf][q] = 0.f;

        for (int c = 0; c < 5; c++) {
            __syncthreads();   // prev chunk mma reads done before overwrite
            // stage h chunk [32][160] with hi/lo split
            {
                const float* hp = hin + sb * HDIM + c*CH + sq*40;
                float* ahp = Ah + sb * AST + sq*40;
                float* alp = Al + sb * AST + sq*40;
                #pragma unroll
                for (int i = 0; i < 40; i += 4) {
                    float4 v = *(const float4*)(hp + i);
                    float h0 = __uint_as_float(f2tf32(v.x));
                    float h1 = __uint_as_float(f2tf32(v.y));
                    float h2 = __uint_as_float(f2tf32(v.z));
                    float h3 = __uint_as_float(f2tf32(v.w));
                    *(float4*)(ahp + i) = make_float4(h0, h1, h2, h3);
                    *(float4*)(alp + i) = make_float4(
                        __uint_as_float(f2tf32(v.x - h0)),
                        __uint_as_float(f2tf32(v.y - h1)),
                        __uint_as_float(f2tf32(v.z - h2)),
                        __uint_as_float(f2tf32(v.w - h3)));
                }
            }
            __syncthreads();

            // mma over warp's k-window within chunk
            #pragma unroll
            for (int kf = 0; kf < 5; kf++) {
                int kl = w*40 + kf*8;        // local col
                int kg = c*CH + kl;          // global k
                unsigned ahf[2][4], alf[2][4];
                #pragma unroll
                for (int mf = 0; mf < 2; mf++) {
                    const float* Ab = Ah + (mf*16 + g)*AST + kl;
                    const float* Lb = Al + (mf*16 + g)*AST + kl;
                    ahf[mf][0] = __float_as_uint(Ab[tig]);
                    ahf[mf][1] = __float_as_uint(Ab[8*AST + tig]);
                    ahf[mf][2] = __float_as_uint(Ab[tig + 4]);
                    ahf[mf][3] = __float_as_uint(Ab[8*AST + tig + 4]);
                    alf[mf][0] = __float_as_uint(Lb[tig]);
                    alf[mf][1] = __float_as_uint(Lb[8*AST + tig]);
                    alf[mf][2] = __float_as_uint(Lb[tig + 4]);
                    alf[mf][3] = __float_as_uint(Lb[8*AST + tig + 4]);
                }
                #pragma unroll
                for (int nf = 0; nf < 2; nf++) {
                    const float2* Wb_ = Wt + (size_t)(nf*8 + g)*HDIM + kg;
                    float2 w0 = Wb_[tig];
                    float2 w1 = Wb_[tig + 4];
                    unsigned bh0 = __float_as_uint(w0.x), bl0 = __float_as_uint(w0.y);
                    unsigned bh1 = __float_as_uint(w1.x), bl1 = __float_as_uint(w1.y);
                    #pragma unroll
                    for (int mf = 0; mf < 2; mf++) {
                        mma_tf32(acc[mf][nf], ahf[mf][0], ahf[mf][1], ahf[mf][2], ahf[mf][3], bh0, bh1);
                        mma_tf32(acc[mf][nf], ahf[mf][0], ahf[mf][1], ahf[mf][2], ahf[mf][3], bl0, bl1);
                        mma_tf32(acc[mf][nf], alf[mf][0], alf[mf][1], alf[mf][2], alf[mf][3], bh0, bh1);
                    }
                }
            }
        }

        // write partial gates: sred[w][batch][row]
        #pragma unroll
        for (int mf = 0; mf < 2; mf++)
            #pragma unroll
            for (int nf = 0; nf < 2; nf++) {
                int b0 = mf*16 + g;
                int r0 = nf*8 + 2*tig;
                float* s = sred + (w*32 + b0)*17 + r0;
                s[0]        = acc[mf][nf][0];
                s[1]        = acc[mf][nf][1];
                s[8*17]     = acc[mf][nf][2];
                s[8*17 + 1] = acc[mf][nf][3];
            }
        __syncthreads();

        // reduce 4 K-partials + cell update (32 batch x 4 units)
        {
            const float* s0 = sred + (0*32 + ub)*17;
            const float* s1 = sred + (1*32 + ub)*17;
            const float* s2 = sred + (2*32 + ub)*17;
            const float* s3 = sred + (3*32 + ub)*17;
            float gi = gin0 + s0[0*4+uu] + s1[0*4+uu] + s2[0*4+uu] + s3[0*4+uu];
            float gf = gin1 + s0[1*4+uu] + s1[1*4+uu] + s2[1*4+uu] + s3[1*4+uu];
            float gg = gin2 + s0[2*4+uu] + s1[2*4+uu] + s2[2*4+uu] + s3[2*4+uu];
            float go = gin3 + s0[3*4+uu] + s1[3*4+uu] + s2[3*4+uu] + s3[3*4+uu];
            float cc = cst[uidx];
            float si = 1.f / (1.f + expf(-gi));
            float sf = 1.f / (1.f + expf(-gf));
            float so = 1.f / (1.f + expf(-go));
            float cn = sf * cc + si * tanhf(gg);
            float hn = so * tanhf(cn);
            cst[uidx] = cn;
            hnx[uidx] = hn;
            hout[((size_t)tt * BATCH + ub) * H2 + dir * HDIM + u0 + uu] = hn;
        }
        __syncthreads();

        // per-(layer,dir) barrier: monotonic counter, 200 arrivals per step
        if (tid == 0) {
            __threadfence();
            atomicAdd(ctr, 1u);
            unsigned target = 200u * (unsigned)(t + 1);
            while (*((volatile unsigned*)ctr) < target) { }
            __threadfence();
        }
        __syncthreads();
    }
}

// ---------------- linear + softmax + angle mixture ------------------------------
__global__ void k_angles(const float* __restrict__ Wlin,
                         const float* __restrict__ blin,
                         const float* __restrict__ alpha)
{
    int w = blockIdx.x * (blockDim.x >> 5) + (threadIdx.x >> 5);
    int lane = threadIdx.x & 31;
    const float* hv = g_h2 + (size_t)w * H2;

    float acc[ASZ];
    #pragma unroll
    for (int j = 0; j < ASZ; j++) acc[j] = 0.f;

    for (int kk = 0; kk < H2 / 32; kk++) {
        float h = hv[lane + kk * 32];
        #pragma unroll
        for (int j = 0; j < ASZ; j++)
            acc[j] = fmaf(h, Wlin[(size_t)j * H2 + lane + kk * 32], acc[j]);
    }
    #pragma unroll
    for (int j = 0; j < ASZ; j++) {
        float v = acc[j];
        #pragma unroll
        for (int s = 16; s; s >>= 1) v += __shfl_xor_sync(0xffffffffu, v, s);
        acc[j] = v + blin[j];
    }
    float mx = acc[0];
    #pragma unroll
    for (int j = 1; j < ASZ; j++) mx = fmaxf(mx, acc[j]);
    float sum = 0.f;
    #pragma unroll
    for (int j = 0; j < ASZ; j++) { acc[j] = expf(acc[j] - mx); sum += acc[j]; }
    float inv = 1.f / sum;

    if (lane < 3) {
        float sm = 0.f, cm = 0.f;
        #pragma unroll
        for (int j = 0; j < ASZ; j++) {
            float p = acc[j] * inv;
            float a = alpha[j * 3 + lane];
            sm = fmaf(p, sinf(a), sm);
            cm = fmaf(p, cosf(a), cm);
        }
        float ang = atan2f(sm, cm);
        int t = w / BATCH, b = w % BATCH;
        g_phi[(t * 3 + lane) * BATCH + b] = ang;
    }
}

// ---------------- NeRF ----------------------------------------------------------
__global__ void k_nerf(float* __restrict__ out)
{
    int b = threadIdx.x;
    const float PI_F = 3.14159265358979323846f;
    const float bl[3] = {1.458f, 1.525f, 1.329f};
    const float ba[3] = {2.124f, 1.941f, 2.028f};
    float ct[3], st[3];
    #pragma unroll
    for (int r = 0; r < 3; r++) { float th = PI_F - ba[r]; ct[r] = cosf(th); st[r] = sinf(th); }

    float ax = 0.f, ay = 0.f, az = 0.f;
    float bx = 1.458f, by = 0.f, bz = 0.f;
    float th0 = PI_F - 2.124f;
    float cx = bx + 1.525f * cosf(th0);
    float cy = 1.525f * sinf(th0);
    float cz = 0.f;

    int r = 0;
    #pragma unroll 1
    for (int i = 0; i < L3; i++) {
        float phi = g_phi[i * BATCH + b];
        float vx = cx - bx, vy = cy - by, vz = cz - bz;
        float n1 = sqrtf(vx*vx + vy*vy + vz*vz);
        float s1 = 1.f / (n1 + 1e-8f);
        float bcx = vx * s1, bcy = vy * s1, bcz = vz * s1;
        float ux = bx - ax, uy = by - ay, uz = bz - az;
        float nx = uy * bcz - uz * bcy;
        float ny = uz * bcx - ux * bcz;
        float nz = ux * bcy - uy * bcx;
        float n2 = sqrtf(nx*nx + ny*ny + nz*nz);
        float s2 = 1.f / (n2 + 1e-8f);
        nx *= s2; ny *= s2; nz *= s2;
        float mx = ny * bcz - nz * bcy;
        float my = nz * bcx - nx * bcz;
        float mz = nx * bcy - ny * bcx;

        float sp, cp;
        sincosf(phi, &sp, &cp);
        float d = bl[r];
        float c_t = ct[r], s_t = st[r];

        float wx = cx + d * (c_t * bcx + s_t * (cp * mx + sp * nx));
        float wy = cy + d * (c_t * bcy + s_t * (cp * my + sp * ny));
        float wz = cz + d * (c_t * bcz + s_t * (cp * mz + sp * nz));

        size_t o = ((size_t)i * BATCH + b) * 3;
        out[o + 0] = wx; out[o + 1] = wy; out[o + 2] = wz;

        ax = bx; ay = by; az = bz;
        bx = cx; by = cy; bz = cz;
        cx = wx; cy = wy; cz = wz;
        r = (r == 2) ? 0 : (r + 1);
    }
}

// ---------------- launch --------------------------------------------------------
extern "C" void kernel_launch(void* const* d_in, const int* in_sizes, int n_in,
                              void* d_out, int out_size)
{
    const float* x     = (const float*)d_in[0];
    const float* Wih0f = (const float*)d_in[1];
    const float* Whh0f = (const float*)d_in[2];
    const float* bih0f = (const float*)d_in[3];
    const float* bhh0f = (const float*)d_in[4];
    const float* Wih0b = (const float*)d_in[5];
    const float* Whh0b = (const float*)d_in[6];
    const float* bih0b = (const float*)d_in[7];
    const float* bhh0b = (const float*)d_in[8];
    const float* Wih1f = (const float*)d_in[9];
    const float* Whh1f = (const float*)d_in[10];
    const float* bih1f = (const float*)d_in[11];
    const float* bhh1f = (const float*)d_in[12];
    const float* Wih1b = (const float*)d_in[13];
    const float* Whh1b = (const float*)d_in[14];
    const float* bih1b = (const float*)d_in[15];
    const float* bhh1b = (const float*)d_in[16];
    const float* W_lin = (const float*)d_in[17];
    const float* b_lin = (const float*)d_in[18];
    const float* alpha = (const float*)d_in[19];

    static int s_attr_done = 0;
    if (!s_attr_done) {
        cudaFuncSetAttribute(k_lstm_mma, cudaFuncAttributeMaxDynamicSharedMemorySize, LSTM_SMEM2);
        s_attr_done = 1;
    }

    k_init<<<800, 256>>>();

    // split recurrence weights (one-time per replay)
    k_wsplit<<<dim3(3200, 2), 256>>>(Whh0f, Whh0b, 0);
    k_wsplit<<<dim3(3200, 2), 256>>>(Whh1f, Whh1b, 1);

    k_proj0<<<dim3(LSEQ * BATCH, 2), 256>>>(x, Wih0f, bih0f, bhh0f, Wih0b, bih0b, bhh0b);

    k_lstm_mma<<<400, 128, LSTM_SMEM2>>>(0);

    k_proj1<<<dim3(G4 / 128, (LSEQ * BATCH) / 128, 2), 256>>>(Wih1f, bih1f, bhh1f,
                                                              Wih1b, bih1b, bhh1b);

    k_lstm_mma<<<400, 128, LSTM_SMEM2>>>(1);

    k_angles<<<(LSEQ * BATCH) / 8, 256>>>(W_lin, b_lin, alpha);

    k_nerf<<<1, 32>>>((float*)d_out);
}

// round 8
// speedup vs baseline: 1.3368x; 1.0495x over previous
#include <cuda_runtime.h>
#include <cuda_bf16.h>
#include <math.h>

#define LSEQ 512
#define BATCH 32
#define DIN 42
#define HDIM 800
#define G4 3200          // 4*HDIM
#define H2 1600          // 2*HDIM
#define ASZ 20
#define L3 (3*LSEQ)

// ---------------- static device scratch (no allocations allowed) ----------------
__device__ float g_G[4][LSEQ*BATCH*G4];
__device__ float g_h1[LSEQ*BATCH*H2];
__device__ float g_h2[LSEQ*BATCH*H2];
__device__ float g_hs[2][2][2][BATCH*HDIM];   // [layer][dir][parity][b*H+u]
__device__ float g_cs[2][2][BATCH*HDIM];      // [layer][dir][b*H+u]
__device__ float g_phi[L3*BATCH];             // [3L][B]
// split recurrence weights: [layer][dir][tile*64*800 + r*800 + k] as (hi,lo)
// local row r = q*16 + du  <->  global gate row q*800 + tile*16 + du
__device__ float2 g_Wsp[2][2][3200*HDIM];
// per-(layer,dir) monotonic barrier counters
__device__ unsigned g_ctr[2][2];

// ---------------- init (graph is replayed; must re-zero) ------------------------
__global__ void k_init()
{
    int i = blockIdx.x * blockDim.x + threadIdx.x;
    if (i < 2*2*2*BATCH*HDIM) ((float*)g_hs)[i] = 0.f;
    if (i < 2*2*BATCH*HDIM)   ((float*)g_cs)[i] = 0.f;
    if (i < 4)                ((unsigned*)g_ctr)[i] = 0u;
}

// ---------------- tf32 helpers --------------------------------------------------
__device__ __forceinline__ unsigned f2tf32(float x)
{
    unsigned r;
    asm("cvt.rna.tf32.f32 %0, %1;" : "=r"(r) : "f"(x));
    return r;
}

__device__ __forceinline__ void mma_tf32(float* d, unsigned a0, unsigned a1, unsigned a2, unsigned a3,
                                         unsigned b0, unsigned b1)
{
    asm volatile("mma.sync.aligned.m16n8k8.row.col.f32.tf32.tf32.f32 "
                 "{%0,%1,%2,%3}, {%4,%5,%6,%7}, {%8,%9}, {%0,%1,%2,%3};"
                 : "+f"(d[0]), "+f"(d[1]), "+f"(d[2]), "+f"(d[3])
                 : "r"(a0), "r"(a1), "r"(a2), "r"(a3), "r"(b0), "r"(b1));
}

// ---------------- split Whh into (hi,lo) tf32 pairs, tile-64 layout -------------
__global__ void k_wsplit(const float* __restrict__ Wf, const float* __restrict__ Wb, int layer)
{
    int dir  = blockIdx.y;
    const float* W = dir ? Wb : Wf;
    int row  = blockIdx.x;          // dest row 0..3199
    int tile = row >> 6;
    int r    = row & 63;
    int q    = r >> 4, du = r & 15;
    const float* src = W + (size_t)(q*HDIM + tile*16 + du) * HDIM;
    float2* dst = g_Wsp[layer][dir] + (size_t)row * HDIM;
    for (int k = threadIdx.x; k < HDIM; k += blockDim.x) {
        float v  = src[k];
        float hi = __uint_as_float(f2tf32(v));
        float lo = __uint_as_float(f2tf32(v - hi));
        dst[k] = make_float2(hi, lo);
    }
}

// ---------------- layer0 input projection --------------------------------------
__global__ void k_proj0(const float* __restrict__ x,
                        const float* __restrict__ Wf, const float* __restrict__ bif, const float* __restrict__ bhf,
                        const float* __restrict__ Wb, const float* __restrict__ bib, const float* __restrict__ bhb)
{
    int tb  = blockIdx.x;
    int dir = blockIdx.y;
    const float* W  = dir ? Wb : Wf;
    const float* b1 = dir ? bib : bif;
    const float* b2 = dir ? bhb : bhf;
    float* G = g_G[dir] + (size_t)tb * G4;

    __shared__ float sx[DIN];
    if (threadIdx.x < DIN) sx[threadIdx.x] = x[(size_t)tb*DIN + threadIdx.x];
    __syncthreads();

    for (int j = threadIdx.x; j < G4; j += blockDim.x) {
        const float* wr = W + (size_t)j * DIN;
        float acc = b1[j] + b2[j];
        #pragma unroll
        for (int k = 0; k < DIN; k++) acc = fmaf(wr[k], sx[k], acc);
        G[j] = acc;
    }
}

// ---------------- layer1 input projection: tf32 tensor-core GEMM ----------------
#define PSTR 20
__global__ void __launch_bounds__(256)
k_proj1(const float* __restrict__ Wf, const float* __restrict__ bif, const float* __restrict__ bhf,
        const float* __restrict__ Wb, const float* __restrict__ bib, const float* __restrict__ bhb)
{
    int dir = blockIdx.z;
    const float* Bm = dir ? Wb : Wf;
    const float* b1 = dir ? bib : bif;
    const float* b2 = dir ? bhb : bhf;
    const float* A  = g_h1;
    float* C = g_G[2 + dir];

    int m0 = blockIdx.y * 128;
    int n0 = blockIdx.x * 128;

    __shared__ float Ah[128*PSTR], Al[128*PSTR], Bh[128*PSTR], Bl[128*PSTR];

    int tid  = threadIdx.x;
    int warp = tid >> 5;
    int lane = tid & 31;
    int g    = lane >> 2;
    int tig  = lane & 3;

    int wm = (warp & 3) * 32;
    int wn = (warp >> 2) * 64;

    int lrow = tid >> 1;
    int lkq  = (tid & 1) * 8;

    float acc[2][8][4];
    #pragma unroll
    for (int i = 0; i < 2; i++)
        #pragma unroll
        for (int j = 0; j < 8; j++)
            #pragma unroll
            for (int q = 0; q < 4; q++) acc[i][j][q] = 0.f;

    float4 av0 = *(const float4*)(A  + (size_t)(m0 + lrow)*H2 + 0 + lkq);
    float4 av1 = *(const float4*)(A  + (size_t)(m0 + lrow)*H2 + 0 + lkq + 4);
    float4 bv0 = *(const float4*)(Bm + (size_t)(n0 + lrow)*H2 + 0 + lkq);
    float4 bv1 = *(const float4*)(Bm + (size_t)(n0 + lrow)*H2 + 0 + lkq + 4);

    for (int it = 0; it < 100; it++) {
        {
            float va[8] = {av0.x, av0.y, av0.z, av0.w, av1.x, av1.y, av1.z, av1.w};
            float vb[8] = {bv0.x, bv0.y, bv0.z, bv0.w, bv1.x, bv1.y, bv1.z, bv1.w};
            #pragma unroll
            for (int j = 0; j < 8; j++) {
                float ahi = __uint_as_float(f2tf32(va[j]));
                float alo = __uint_as_float(f2tf32(va[j] - ahi));
                Ah[lrow*PSTR + lkq + j] = ahi;
                Al[lrow*PSTR + lkq + j] = alo;
                float bhi = __uint_as_float(f2tf32(vb[j]));
                float blo = __uint_as_float(f2tf32(vb[j] - bhi));
                Bh[lrow*PSTR + lkq + j] = bhi;
                Bl[lrow*PSTR + lkq + j] = blo;
            }
        }
        __syncthreads();

        if (it < 99) {
            int k0 = (it + 1) * 16;
            av0 = *(const float4*)(A  + (size_t)(m0 + lrow)*H2 + k0 + lkq);
            av1 = *(const float4*)(A  + (size_t)(m0 + lrow)*H2 + k0 + lkq + 4);
            bv0 = *(const float4*)(Bm + (size_t)(n0 + lrow)*H2 + k0 + lkq);
            bv1 = *(const float4*)(Bm + (size_t)(n0 + lrow)*H2 + k0 + lkq + 4);
        }

        #pragma unroll
        for (int kk = 0; kk < 16; kk += 8) {
            unsigned ah[2][4], al[2][4];
            #pragma unroll
            for (int mf = 0; mf < 2; mf++) {
                int r0 = wm + mf*16 + g;
                int r1 = r0 + 8;
                int c0 = kk + tig, c1 = kk + tig + 4;
                ah[mf][0] = __float_as_uint(Ah[r0*PSTR + c0]);
                ah[mf][1] = __float_as_uint(Ah[r1*PSTR + c0]);
                ah[mf][2] = __float_as_uint(Ah[r0*PSTR + c1]);
                ah[mf][3] = __float_as_uint(Ah[r1*PSTR + c1]);
                al[mf][0] = __float_as_uint(Al[r0*PSTR + c0]);
                al[mf][1] = __float_as_uint(Al[r1*PSTR + c0]);
                al[mf][2] = __float_as_uint(Al[r0*PSTR + c1]);
                al[mf][3] = __float_as_uint(Al[r1*PSTR + c1]);
            }
            #pragma unroll
            for (int nf = 0; nf < 8; nf++) {
                int n = wn + nf*8 + g;
                unsigned bh0 = __float_as_uint(Bh[n*PSTR + kk + tig]);
                unsigned bh1 = __float_as_uint(Bh[n*PSTR + kk + tig + 4]);
                unsigned bl0 = __float_as_uint(Bl[n*PSTR + kk + tig]);
                unsigned bl1 = __float_as_uint(Bl[n*PSTR + kk + tig + 4]);
                #pragma unroll
                for (int mf = 0; mf < 2; mf++) {
                    mma_tf32(acc[mf][nf], ah[mf][0], ah[mf][1], ah[mf][2], ah[mf][3], bh0, bh1);
                    mma_tf32(acc[mf][nf], ah[mf][0], ah[mf][1], ah[mf][2], ah[mf][3], bl0, bl1);
                    mma_tf32(acc[mf][nf], al[mf][0], al[mf][1], al[mf][2], al[mf][3], bh0, bh1);
                }
            }
        }
        __syncthreads();
    }

    #pragma unroll
    for (int mf = 0; mf < 2; mf++) {
        int r0 = m0 + wm + mf*16 + g;
        #pragma unroll
        for (int nf = 0; nf < 8; nf++) {
            int col = n0 + wn + nf*8 + 2*tig;
            float bb0 = b1[col]   + b2[col];
            float bb1 = b1[col+1] + b2[col+1];
            float2 v0 = make_float2(acc[mf][nf][0] + bb0, acc[mf][nf][1] + bb1);
            float2 v1 = make_float2(acc[mf][nf][2] + bb0, acc[mf][nf][3] + bb1);
            *(float2*)(C + (size_t)r0*G4 + col)     = v0;
            *(float2*)(C + (size_t)(r0+8)*G4 + col) = v1;
        }
    }
}

// ---------------- persistent bi-LSTM recurrence on tensor cores -----------------
// 100 blocks = 50 tiles (16 units = 64 gate rows) x 2 dirs; 128 threads.
// 1 block/SM (136 KB smem). Warp w handles K-slice [w*200, w*200+200).
// Gates[32 batch x 64 rows] = h[32x800] @ Wtile[64x800]^T via tf32 3-term mma.
#define NBLKD 50u
#define HST 804            // h smem stride (804 mod 32 = 4 -> conflict-free frags)
#define RST 65             // sred row stride
#define LSTM_SMEM3 ((32*HST + 4*32*RST) * 4)
__global__ void __launch_bounds__(128, 1)
k_lstm_mma(int layer)
{
    extern __shared__ float dsm[];
    float* hraw = dsm;                 // [32][804] raw fp32 h
    float* sred = dsm + 32*HST;        // [4][32][65] partial gates

    int dir  = blockIdx.x & 1;
    int tile = blockIdx.x >> 1;        // 0..49
    int u0   = tile * 16;

    const float2* Wt   = g_Wsp[layer][dir] + (size_t)tile * 64 * HDIM;
    const float* Gbase = g_G[layer*2 + dir];
    float* cst  = g_cs[layer][dir];
    float* hout = layer ? g_h2 : g_h1;
    float* hb0  = g_hs[layer][dir][0];
    float* hb1  = g_hs[layer][dir][1];
    unsigned* ctr = &g_ctr[layer][dir];

    int tid  = threadIdx.x;
    int lane = tid & 31;
    int w    = tid >> 5;          // warp = K-slice
    int g    = lane >> 2;         // 0..7
    int tig  = lane & 3;          // 0..3
    int kw0  = w * 200;

    // h staging ids: 32 rows x 4 k-quarters of 200
    int sb = tid >> 2;
    int sq = tid & 3;
    // cell ids: 32 batch x 4 unit-groups of 4
    int ub = tid & 31;
    int uu = tid >> 5;

    for (int t = 0; t < LSEQ; t++) {
        int tt = dir ? (LSEQ - 1 - t) : t;
        const float* hin = (t & 1) ? hb1 : hb0;
        float*       hnx = (t & 1) ? hb0 : hb1;
        const float* G   = Gbase + (size_t)tt * (BATCH * G4);

        // prefetch input-gate values for this thread's 4 cells
        float gin[4][4];
        #pragma unroll
        for (int i = 0; i < 4; i++) {
            int du = uu*4 + i;
            const float* gp = G + (size_t)ub * G4 + u0 + du;
            #pragma unroll
            for (int q = 0; q < 4; q++) gin[i][q] = gp[q*HDIM];
        }

        // stage h (raw fp32) into smem
        {
            const float* hp = hin + sb * HDIM + sq * 200;
            float* sp = hraw + sb * HST + sq * 200;
            #pragma unroll 10
            for (int j = 0; j < 200; j += 4) {
                float4 v = *(const float4*)(hp + j);
                *(float4*)(sp + j) = v;
            }
        }
        __syncthreads();

        float acc[2][8][4];
        #pragma unroll
        for (int mf = 0; mf < 2; mf++)
            #pragma unroll
            for (int nf = 0; nf < 8; nf++)
                #pragma unroll
                for (int q = 0; q < 4; q++) acc[mf][nf][q] = 0.f;

        #pragma unroll 5
        for (int kt = 0; kt < 25; kt++) {
            int kk = kw0 + kt * 8;
            // a-frags: raw from smem, split to hi/lo in regs
            unsigned ah[2][4], al[2][4];
            #pragma unroll
            for (int mf = 0; mf < 2; mf++) {
                const float* ab = hraw + (mf*16 + g) * HST + kk;
                float r0 = ab[tig];
                float r1 = ab[8*HST + tig];
                float r2 = ab[tig + 4];
                float r3 = ab[8*HST + tig + 4];
                ah[mf][0] = f2tf32(r0); al[mf][0] = f2tf32(r0 - __uint_as_float(ah[mf][0]));
                ah[mf][1] = f2tf32(r1); al[mf][1] = f2tf32(r1 - __uint_as_float(ah[mf][1]));
                ah[mf][2] = f2tf32(r2); al[mf][2] = f2tf32(r2 - __uint_as_float(ah[mf][2]));
                ah[mf][3] = f2tf32(r3); al[mf][3] = f2tf32(r3 - __uint_as_float(ah[mf][3]));
            }
            #pragma unroll
            for (int nf = 0; nf < 8; nf++) {
                const float2* wp = Wt + (size_t)(nf*8 + g) * HDIM + kk;
                float2 w0 = wp[tig];
                float2 w1 = wp[tig + 4];
                unsigned bh0 = __float_as_uint(w0.x), bl0 = __float_as_uint(w0.y);
                unsigned bh1 = __float_as_uint(w1.x), bl1 = __float_as_uint(w1.y);
                #pragma unroll
                for (int mf = 0; mf < 2; mf++) {
                    mma_tf32(acc[mf][nf], ah[mf][0], ah[mf][1], ah[mf][2], ah[mf][3], bh0, bh1);
                    mma_tf32(acc[mf][nf], ah[mf][0], ah[mf][1], ah[mf][2], ah[mf][3], bl0, bl1);
                    mma_tf32(acc[mf][nf], al[mf][0], al[mf][1], al[mf][2], al[mf][3], bh0, bh1);
                }
            }
        }

        // write partial gates: sred[w][batch][row]
        #pragma unroll
        for (int mf = 0; mf < 2; mf++)
            #pragma unroll
            for (int nf = 0; nf < 8; nf++) {
                float* s = sred + ((w*32 + mf*16 + g) * RST + nf*8 + 2*tig);
                s[0]          = acc[mf][nf][0];
                s[1]          = acc[mf][nf][1];
                s[8*RST]      = acc[mf][nf][2];
                s[8*RST + 1]  = acc[mf][nf][3];
            }
        __syncthreads();

        // reduce 4 K-partials + cell update: each thread 4 cells (b=ub, du=uu*4+i)
        #pragma unroll
        for (int i = 0; i < 4; i++) {
            int du = uu*4 + i;
            float gt[4];
            #pragma unroll
            for (int q = 0; q < 4; q++) {
                int r = q*16 + du;
                gt[q] = gin[i][q]
                      + sred[(0*32 + ub)*RST + r]
                      + sred[(1*32 + ub)*RST + r]
                      + sred[(2*32 + ub)*RST + r]
                      + sred[(3*32 + ub)*RST + r];
            }
            int uidx = ub * HDIM + u0 + du;
            float cc = cst[uidx];
            float si = 1.f / (1.f + expf(-gt[0]));
            float sf = 1.f / (1.f + expf(-gt[1]));
            float so = 1.f / (1.f + expf(-gt[3]));
            float cn = sf * cc + si * tanhf(gt[2]);
            float hn = so * tanhf(cn);
            cst[uidx] = cn;
            hnx[uidx] = hn;
            hout[((size_t)tt * BATCH + ub) * H2 + dir * HDIM + u0 + du] = hn;
        }
        __syncthreads();

        // per-(layer,dir) barrier: monotonic counter, NBLKD arrivals per step
        if (tid == 0) {
            __threadfence();
            atomicAdd(ctr, 1u);
            unsigned target = NBLKD * (unsigned)(t + 1);
            while (*((volatile unsigned*)ctr) < target) { }
            __threadfence();
        }
        __syncthreads();
    }
}

// ---------------- linear + softmax + angle mixture ------------------------------
__global__ void k_angles(const float* __restrict__ Wlin,
                         const float* __restrict__ blin,
                         const float* __restrict__ alpha)
{
    int w = blockIdx.x * (blockDim.x >> 5) + (threadIdx.x >> 5);
    int lane = threadIdx.x & 31;
    const float* hv = g_h2 + (size_t)w * H2;

    float acc[ASZ];
    #pragma unroll
    for (int j = 0; j < ASZ; j++) acc[j] = 0.f;

    for (int kk = 0; kk < H2 / 32; kk++) {
        float h = hv[lane + kk * 32];
        #pragma unroll
        for (int j = 0; j < ASZ; j++)
            acc[j] = fmaf(h, Wlin[(size_t)j * H2 + lane + kk * 32], acc[j]);
    }
    #pragma unroll
    for (int j = 0; j < ASZ; j++) {
        float v = acc[j];
        #pragma unroll
        for (int s = 16; s; s >>= 1) v += __shfl_xor_sync(0xffffffffu, v, s);
        acc[j] = v + blin[j];
    }
    float mx = acc[0];
    #pragma unroll
    for (int j = 1; j < ASZ; j++) mx = fmaxf(mx, acc[j]);
    float sum = 0.f;
    #pragma unroll
    for (int j = 0; j < ASZ; j++) { acc[j] = expf(acc[j] - mx); sum += acc[j]; }
    float inv = 1.f / sum;

    if (lane < 3) {
        float sm = 0.f, cm = 0.f;
        #pragma unroll
        for (int j = 0; j < ASZ; j++) {
            float p = acc[j] * inv;
            float a = alpha[j * 3 + lane];
            sm = fmaf(p, sinf(a), sm);
            cm = fmaf(p, cosf(a), cm);
        }
        float ang = atan2f(sm, cm);
        int t = w / BATCH, b = w % BATCH;
        g_phi[(t * 3 + lane) * BATCH + b] = ang;
    }
}

// ---------------- NeRF ----------------------------------------------------------
__global__ void k_nerf(float* __restrict__ out)
{
    int b = threadIdx.x;
    const float PI_F = 3.14159265358979323846f;
    const float bl[3] = {1.458f, 1.525f, 1.329f};
    const float ba[3] = {2.124f, 1.941f, 2.028f};
    float ct[3], st[3];
    #pragma unroll
    for (int r = 0; r < 3; r++) { float th = PI_F - ba[r]; ct[r] = cosf(th); st[r] = sinf(th); }

    float ax = 0.f, ay = 0.f, az = 0.f;
    float bx = 1.458f, by = 0.f, bz = 0.f;
    float th0 = PI_F - 2.124f;
    float cx = bx + 1.525f * cosf(th0);
    float cy = 1.525f * sinf(th0);
    float cz = 0.f;

    int r = 0;
    #pragma unroll 1
    for (int i = 0; i < L3; i++) {
        float phi = g_phi[i * BATCH + b];
        float vx = cx - bx, vy = cy - by, vz = cz - bz;
        float n1 = sqrtf(vx*vx + vy*vy + vz*vz);
        float s1 = 1.f / (n1 + 1e-8f);
        float bcx = vx * s1, bcy = vy * s1, bcz = vz * s1;
        float ux = bx - ax, uy = by - ay, uz = bz - az;
        float nx = uy * bcz - uz * bcy;
        float ny = uz * bcx - ux * bcz;
        float nz = ux * bcy - uy * bcx;
        float n2 = sqrtf(nx*nx + ny*ny + nz*nz);
        float s2 = 1.f / (n2 + 1e-8f);
        nx *= s2; ny *= s2; nz *= s2;
        float mx = ny * bcz - nz * bcy;
        float my = nz * bcx - nx * bcz;
        float mz = nx * bcy - ny * bcx;

        float sp, cp;
        sincosf(phi, &sp, &cp);
        float d = bl[r];
        float c_t = ct[r], s_t = st[r];

        float wx = cx + d * (c_t * bcx + s_t * (cp * mx + sp * nx));
        float wy = cy + d * (c_t * bcy + s_t * (cp * my + sp * ny));
        float wz = cz + d * (c_t * bcz + s_t * (cp * mz + sp * nz));

        size_t o = ((size_t)i * BATCH + b) * 3;
        out[o + 0] = wx; out[o + 1] = wy; out[o + 2] = wz;

        ax = bx; ay = by; az = bz;
        bx = cx; by = cy; bz = cz;
        cx = wx; cy = wy; cz = wz;
        r = (r == 2) ? 0 : (r + 1);
    }
}

// ---------------- launch --------------------------------------------------------
extern "C" void kernel_launch(void* const* d_in, const int* in_sizes, int n_in,
                              void* d_out, int out_size)
{
    const float* x     = (const float*)d_in[0];
    const float* Wih0f = (const float*)d_in[1];
    const float* Whh0f = (const float*)d_in[2];
    const float* bih0f = (const float*)d_in[3];
    const float* bhh0f = (const float*)d_in[4];
    const float* Wih0b = (const float*)d_in[5];
    const float* Whh0b = (const float*)d_in[6];
    const float* bih0b = (const float*)d_in[7];
    const float* bhh0b = (const float*)d_in[8];
    const float* Wih1f = (const float*)d_in[9];
    const float* Whh1f = (const float*)d_in[10];
    const float* bih1f = (const float*)d_in[11];
    const float* bhh1f = (const float*)d_in[12];
    const float* Wih1b = (const float*)d_in[13];
    const float* Whh1b = (const float*)d_in[14];
    const float* bih1b = (const float*)d_in[15];
    const float* bhh1b = (const float*)d_in[16];
    const float* W_lin = (const float*)d_in[17];
    const float* b_lin = (const float*)d_in[18];
    const float* alpha = (const float*)d_in[19];

    static int s_attr_done = 0;
    if (!s_attr_done) {
        cudaFuncSetAttribute(k_lstm_mma, cudaFuncAttributeMaxDynamicSharedMemorySize, LSTM_SMEM3);
        s_attr_done = 1;
    }

    k_init<<<800, 256>>>();

    // split recurrence weights (tile-64 layout)
    k_wsplit<<<dim3(3200, 2), 256>>>(Whh0f, Whh0b, 0);
    k_wsplit<<<dim3(3200, 2), 256>>>(Whh1f, Whh1b, 1);

    k_proj0<<<dim3(LSEQ * BATCH, 2), 256>>>(x, Wih0f, bih0f, bhh0f, Wih0b, bih0b, bhh0b);

    k_lstm_mma<<<2 * NBLKD, 128, LSTM_SMEM3>>>(0);

    k_proj1<<<dim3(G4 / 128, (LSEQ * BATCH) / 128, 2), 256>>>(Wih1f, bih1f, bhh1f,
                                                              Wih1b, bih1b, bhh1b);

    k_lstm_mma<<<2 * NBLKD, 128, LSTM_SMEM3>>>(1);

    k_angles<<<(LSEQ * BATCH) / 8, 256>>>(W_lin, b_lin, alpha);

    k_nerf<<<1, 32>>>((float*)d_out);
}

// round 10
// speedup vs baseline: 1.7356x; 1.2984x over previous
#include <cuda_runtime.h>
#include <cuda_bf16.h>
#include <cuda_fp16.h>
#include <math.h>

#define LSEQ 512
#define BATCH 32
#define DIN 42
#define HDIM 800
#define G4 3200          // 4*HDIM
#define H2 1600          // 2*HDIM
#define ASZ 20
#define L3 (3*LSEQ)

// ---------------- static device scratch (no allocations allowed) ----------------
__device__ float g_G[4][LSEQ*BATCH*G4];
__device__ float g_h1[LSEQ*BATCH*H2];
__device__ float g_h2[LSEQ*BATCH*H2];
__device__ float g_hs[2][2][2][BATCH*HDIM];   // [layer][dir][parity][b*H+u]
__device__ float g_cs[2][2][BATCH*HDIM];      // [layer][dir][b*H+u]
__device__ float g_phi[L3*BATCH];             // [3L][B]
// fp16-split W in mma fragment order:
// [layer][dir][((tile*50 + kt)*8 + nf)*32 + lane] = {b0_hi, b1_hi, b0_lo*2048, b1_lo*2048}
__device__ uint4 g_Wfrag[2][2][50*50*8*32];
// per-(layer,dir) monotonic barrier counters
__device__ unsigned g_ctr[2][2];

// ---------------- init (graph is replayed; must re-zero) ------------------------
__global__ void k_init()
{
    int i = blockIdx.x * blockDim.x + threadIdx.x;
    if (i < 2*2*2*BATCH*HDIM) ((float*)g_hs)[i] = 0.f;
    if (i < 2*2*BATCH*HDIM)   ((float*)g_cs)[i] = 0.f;
    if (i < 4)                ((unsigned*)g_ctr)[i] = 0u;
}

// ---------------- tf32 / fp16 helpers -------------------------------------------
__device__ __forceinline__ unsigned f2tf32(float x)
{
    unsigned r;
    asm("cvt.rna.tf32.f32 %0, %1;" : "=r"(r) : "f"(x));
    return r;
}

__device__ __forceinline__ void mma_tf32(float* d, unsigned a0, unsigned a1, unsigned a2, unsigned a3,
                                         unsigned b0, unsigned b1)
{
    asm volatile("mma.sync.aligned.m16n8k8.row.col.f32.tf32.tf32.f32 "
                 "{%0,%1,%2,%3}, {%4,%5,%6,%7}, {%8,%9}, {%0,%1,%2,%3};"
                 : "+f"(d[0]), "+f"(d[1]), "+f"(d[2]), "+f"(d[3])
                 : "r"(a0), "r"(a1), "r"(a2), "r"(a3), "r"(b0), "r"(b1));
}

__device__ __forceinline__ void mma_f16(float* d, const unsigned* a, unsigned b0, unsigned b1)
{
    asm volatile("mma.sync.aligned.m16n8k16.row.col.f32.f16.f16.f32 "
                 "{%0,%1,%2,%3}, {%4,%5,%6,%7}, {%8,%9}, {%0,%1,%2,%3};"
                 : "+f"(d[0]), "+f"(d[1]), "+f"(d[2]), "+f"(d[3])
                 : "r"(a[0]), "r"(a[1]), "r"(a[2]), "r"(a[3]), "r"(b0), "r"(b1));
}

__device__ __forceinline__ unsigned packh2(half a, half b)
{
    __half2 h = __halves2half2(a, b);
    return *(unsigned*)&h;
}

// ---------------- build fp16-split W fragments ----------------------------------
// grid (2500, 2): blk = tile*50 + kt; 256 threads = 8 nf x 32 lanes
__global__ void k_wfrag(const float* __restrict__ Wf, const float* __restrict__ Wb, int layer)
{
    int dir = blockIdx.y;
    const float* W = dir ? Wb : Wf;
    int blk  = blockIdx.x;
    int tile = blk / 50, kt = blk % 50;
    int tid  = threadIdx.x;
    int nf   = tid >> 5, lane = tid & 31;
    int g    = lane >> 2, tig = lane & 3;
    int r    = nf*8 + g;
    int q    = r >> 4, du = r & 15;
    const float* row = W + (size_t)(q*HDIM + tile*16 + du) * HDIM + kt*16;
    float e0 = row[2*tig], e1 = row[2*tig+1], e2 = row[8+2*tig], e3 = row[9+2*tig];
    half h0 = __float2half_rn(e0); half l0 = __float2half_rn((e0 - __half2float(h0)) * 2048.f);
    half h1 = __float2half_rn(e1); half l1 = __float2half_rn((e1 - __half2float(h1)) * 2048.f);
    half h2 = __float2half_rn(e2); half l2 = __float2half_rn((e2 - __half2float(h2)) * 2048.f);
    half h3 = __float2half_rn(e3); half l3 = __float2half_rn((e3 - __half2float(h3)) * 2048.f);
    uint4 out;
    out.x = packh2(h0, h1);
    out.y = packh2(h2, h3);
    out.z = packh2(l0, l1);
    out.w = packh2(l2, l3);
    g_Wfrag[layer][dir][(size_t)((tile*50 + kt)*8 + nf)*32 + lane] = out;
}

// ---------------- layer0 input projection (W-reuse tiled) -----------------------
// grid (512, 16, 2): 32 tb-pairs x 200 gate rows per block, 256 threads
__global__ void __launch_bounds__(256)
k_proj0(const float* __restrict__ x,
        const float* __restrict__ Wf, const float* __restrict__ bif, const float* __restrict__ bhf,
        const float* __restrict__ Wb, const float* __restrict__ bib, const float* __restrict__ bhb)
{
    int tb0 = blockIdx.x * 32;
    int j0  = blockIdx.y * 200;
    int dir = blockIdx.z;
    const float* W  = dir ? Wb : Wf;
    const float* b1 = dir ? bib : bif;
    const float* b2 = dir ? bhb : bhf;
    float* G = g_G[dir];

    __shared__ float sx[32*43];
    for (int idx = threadIdx.x; idx < 32*DIN; idx += 256) {
        int tb = idx / DIN, k = idx % DIN;
        sx[tb*43 + k] = x[(size_t)(tb0 + tb)*DIN + k];
    }
    __syncthreads();

    #pragma unroll 1
    for (int i = 0; i < 25; i++) {
        int o  = i*256 + threadIdx.x;    // 0..6399
        int j  = o >> 5;                 // warp-uniform
        int tb = o & 31;
        const float* wr = W + (size_t)(j0 + j) * DIN;
        float acc = b1[j0+j] + b2[j0+j];
        #pragma unroll
        for (int k = 0; k < DIN; k++) acc = fmaf(wr[k], sx[tb*43 + k], acc);
        G[(size_t)(tb0 + tb)*G4 + j0 + j] = acc;
    }
}

// ---------------- layer1 input projection: tf32 tensor-core GEMM ----------------
#define PSTR 20
__global__ void __launch_bounds__(256)
k_proj1(const float* __restrict__ Wf, const float* __restrict__ bif, const float* __restrict__ bhf,
        const float* __restrict__ Wb, const float* __restrict__ bib, const float* __restrict__ bhb)
{
    int dir = blockIdx.z;
    const float* Bm = dir ? Wb : Wf;
    const float* b1 = dir ? bib : bif;
    const float* b2 = dir ? bhb : bhf;
    const float* A  = g_h1;
    float* C = g_G[2 + dir];

    int m0 = blockIdx.y * 128;
    int n0 = blockIdx.x * 128;

    __shared__ float Ah[128*PSTR], Al[128*PSTR], Bh[128*PSTR], Bl[128*PSTR];

    int tid  = threadIdx.x;
    int warp = tid >> 5;
    int lane = tid & 31;
    int g    = lane >> 2;
    int tig  = lane & 3;

    int wm = (warp & 3) * 32;
    int wn = (warp >> 2) * 64;

    int lrow = tid >> 1;
    int lkq  = (tid & 1) * 8;

    float acc[2][8][4];
    #pragma unroll
    for (int i = 0; i < 2; i++)
        #pragma unroll
        for (int j = 0; j < 8; j++)
            #pragma unroll
            for (int q = 0; q < 4; q++) acc[i][j][q] = 0.f;

    float4 av0 = *(const float4*)(A  + (size_t)(m0 + lrow)*H2 + 0 + lkq);
    float4 av1 = *(const float4*)(A  + (size_t)(m0 + lrow)*H2 + 0 + lkq + 4);
    float4 bv0 = *(const float4*)(Bm + (size_t)(n0 + lrow)*H2 + 0 + lkq);
    float4 bv1 = *(const float4*)(Bm + (size_t)(n0 + lrow)*H2 + 0 + lkq + 4);

    for (int it = 0; it < 100; it++) {
        {
            float va[8] = {av0.x, av0.y, av0.z, av0.w, av1.x, av1.y, av1.z, av1.w};
            float vb[8] = {bv0.x, bv0.y, bv0.z, bv0.w, bv1.x, bv1.y, bv1.z, bv1.w};
            #pragma unroll
            for (int j = 0; j < 8; j++) {
                float ahi = __uint_as_float(f2tf32(va[j]));
                float alo = __uint_as_float(f2tf32(va[j] - ahi));
                Ah[lrow*PSTR + lkq + j] = ahi;
                Al[lrow*PSTR + lkq + j] = alo;
                float bhi = __uint_as_float(f2tf32(vb[j]));
                float blo = __uint_as_float(f2tf32(vb[j] - bhi));
                Bh[lrow*PSTR + lkq + j] = bhi;
                Bl[lrow*PSTR + lkq + j] = blo;
            }
        }
        __syncthreads();

        if (it < 99) {
            int k0 = (it + 1) * 16;
            av0 = *(const float4*)(A  + (size_t)(m0 + lrow)*H2 + k0 + lkq);
            av1 = *(const float4*)(A  + (size_t)(m0 + lrow)*H2 + k0 + lkq + 4);
            bv0 = *(const float4*)(Bm + (size_t)(n0 + lrow)*H2 + k0 + lkq);
            bv1 = *(const float4*)(Bm + (size_t)(n0 + lrow)*H2 + k0 + lkq + 4);
        }

        #pragma unroll
        for (int kk = 0; kk < 16; kk += 8) {
            unsigned ah[2][4], al[2][4];
            #pragma unroll
            for (int mf = 0; mf < 2; mf++) {
                int r0 = wm + mf*16 + g;
                int r1 = r0 + 8;
                int c0 = kk + tig, c1 = kk + tig + 4;
                ah[mf][0] = __float_as_uint(Ah[r0*PSTR + c0]);
                ah[mf][1] = __float_as_uint(Ah[r1*PSTR + c0]);
                ah[mf][2] = __float_as_uint(Ah[r0*PSTR + c1]);
                ah[mf][3] = __float_as_uint(Ah[r1*PSTR + c1]);
                al[mf][0] = __float_as_uint(Al[r0*PSTR + c0]);
                al[mf][1] = __float_as_uint(Al[r1*PSTR + c0]);
                al[mf][2] = __float_as_uint(Al[r0*PSTR + c1]);
                al[mf][3] = __float_as_uint(Al[r1*PSTR + c1]);
            }
            #pragma unroll
            for (int nf = 0; nf < 8; nf++) {
                int n = wn + nf*8 + g;
                unsigned bh0 = __float_as_uint(Bh[n*PSTR + kk + tig]);
                unsigned bh1 = __float_as_uint(Bh[n*PSTR + kk + tig + 4]);
                unsigned bl0 = __float_as_uint(Bl[n*PSTR + kk + tig]);
                unsigned bl1 = __float_as_uint(Bl[n*PSTR + kk + tig + 4]);
                #pragma unroll
                for (int mf = 0; mf < 2; mf++) {
                    mma_tf32(acc[mf][nf], ah[mf][0], ah[mf][1], ah[mf][2], ah[mf][3], bh0, bh1);
                    mma_tf32(acc[mf][nf], ah[mf][0], ah[mf][1], ah[mf][2], ah[mf][3], bl0, bl1);
                    mma_tf32(acc[mf][nf], al[mf][0], al[mf][1], al[mf][2], al[mf][3], bh0, bh1);
                }
            }
        }
        __syncthreads();
    }

    #pragma unroll
    for (int mf = 0; mf < 2; mf++) {
        int r0 = m0 + wm + mf*16 + g;
        #pragma unroll
        for (int nf = 0; nf < 8; nf++) {
            int col = n0 + wn + nf*8 + 2*tig;
            float bb0 = b1[col]   + b2[col];
            float bb1 = b1[col+1] + b2[col+1];
            float2 v0 = make_float2(acc[mf][nf][0] + bb0, acc[mf][nf][1] + bb1);
            float2 v1 = make_float2(acc[mf][nf][2] + bb0, acc[mf][nf][3] + bb1);
            *(float2*)(C + (size_t)r0*G4 + col)     = v0;
            *(float2*)(C + (size_t)(r0+8)*G4 + col) = v1;
        }
    }
}

// ---------------- persistent bi-LSTM recurrence: fp16 2-word split mma ----------
// 100 blocks = 50 tiles(16 units) x 2 dirs; 128 threads; 1 block/SM.
// Warp w: kslice = w&1 (K half, 25 k16-tiles), nhalf = w>>1 (32 of 64 gate rows).
#define NBLKD 50u
#define HPAD 808
#define RST2 68
#define LSTM_SMEM4 (2*32*HPAD*2 + 2*32*RST2*4)
__global__ void __launch_bounds__(128, 1)
k_lstm_mma(int layer)
{
    extern __shared__ char dsmc[];
    half*  hhi  = (half*)dsmc;                 // [32][HPAD]
    half*  hlo  = hhi + 32*HPAD;               // [32][HPAD]  (scaled by 2048)
    float* sred = (float*)(hlo + 32*HPAD);     // [2][32][RST2]

    int dir  = blockIdx.x & 1;
    int tile = blockIdx.x >> 1;
    int u0   = tile * 16;

    const uint4* Wf    = g_Wfrag[layer][dir] + (size_t)tile * 50 * 8 * 32;
    const float* Gbase = g_G[layer*2 + dir];
    float* cst  = g_cs[layer][dir];
    float* hout = layer ? g_h2 : g_h1;
    float* hb0  = g_hs[layer][dir][0];
    float* hb1  = g_hs[layer][dir][1];
    unsigned* ctr = &g_ctr[layer][dir];

    int tid  = threadIdx.x;
    int lane = tid & 31;
    int w    = tid >> 5;
    int g    = lane >> 2;
    int tig  = lane & 3;
    int kslice = w & 1;
    int nhalf  = w >> 1;

    // staging ids: 32 rows x 4 k-quarters(200)
    int sb = tid >> 2;
    int sq = tid & 3;
    // cell ids
    int ub = tid & 31;
    int uu = tid >> 5;

    const float INV2K = 1.f / 2048.f;

    for (int t = 0; t < LSEQ; t++) {
        int tt = dir ? (LSEQ - 1 - t) : t;
        const float* hin = (t & 1) ? hb1 : hb0;
        float*       hnx = (t & 1) ? hb0 : hb1;
        const float* G   = Gbase + (size_t)tt * (BATCH * G4);

        // prefetch input-gate values for this thread's 4 cells
        float gin[4][4];
        #pragma unroll
        for (int i = 0; i < 4; i++) {
            int du = uu*4 + i;
            const float* gp = G + (size_t)ub * G4 + u0 + du;
            #pragma unroll
            for (int q = 0; q < 4; q++) gin[i][q] = gp[q*HDIM];
        }

        // stage h into smem as fp16 hi/lo (lo scaled by 2048)
        {
            const float* hp = hin + sb * HDIM + sq * 200;
            half* hh = hhi + sb * HPAD + sq * 200;
            half* hl = hlo + sb * HPAD + sq * 200;
            #pragma unroll 5
            for (int j = 0; j < 200; j += 4) {
                float4 v = *(const float4*)(hp + j);
                half a0 = __float2half_rn(v.x); half b0 = __float2half_rn((v.x - __half2float(a0)) * 2048.f);
                half a1 = __float2half_rn(v.y); half b1 = __float2half_rn((v.y - __half2float(a1)) * 2048.f);
                half a2 = __float2half_rn(v.z); half b2 = __float2half_rn((v.z - __half2float(a2)) * 2048.f);
                half a3 = __float2half_rn(v.w); half b3 = __float2half_rn((v.w - __half2float(a3)) * 2048.f);
                *(unsigned*)(hh + j)     = packh2(a0, a1);
                *(unsigned*)(hh + j + 2) = packh2(a2, a3);
                *(unsigned*)(hl + j)     = packh2(b0, b1);
                *(unsigned*)(hl + j + 2) = packh2(b2, b3);
            }
        }
        __syncthreads();

        float ahh[2][4][4], ahl[2][4][4], alh[2][4][4];
        #pragma unroll
        for (int mf = 0; mf < 2; mf++)
            #pragma unroll
            for (int nfl = 0; nfl < 4; nfl++)
                #pragma unroll
                for (int q = 0; q < 4; q++) { ahh[mf][nfl][q] = 0.f; ahl[mf][nfl][q] = 0.f; alh[mf][nfl][q] = 0.f; }

        // W fragment double buffer
        uint4 wc[4], wn_[4];
        #pragma unroll
        for (int nfl = 0; nfl < 4; nfl++)
            wc[nfl] = Wf[(size_t)((kslice*25)*8 + nhalf*4 + nfl)*32 + lane];

        #pragma unroll 5
        for (int ktl = 0; ktl < 25; ktl++) {
            int kt = kslice*25 + ktl;
            if (ktl < 24) {
                #pragma unroll
                for (int nfl = 0; nfl < 4; nfl++)
                    wn_[nfl] = Wf[(size_t)((kt+1)*8 + nhalf*4 + nfl)*32 + lane];
            }

            // A fragments from smem (hi and scaled-lo)
            unsigned ah[2][4], al[2][4];
            int k0 = kt * 16;
            #pragma unroll
            for (int mf = 0; mf < 2; mf++) {
                const half* ph = hhi + (mf*16 + g)*HPAD + k0 + 2*tig;
                const half* pl = hlo + (mf*16 + g)*HPAD + k0 + 2*tig;
                ah[mf][0] = *(const unsigned*)(ph);
                ah[mf][1] = *(const unsigned*)(ph + 8*HPAD);
                ah[mf][2] = *(const unsigned*)(ph + 8);
                ah[mf][3] = *(const unsigned*)(ph + 8*HPAD + 8);
                al[mf][0] = *(const unsigned*)(pl);
                al[mf][1] = *(const unsigned*)(pl + 8*HPAD);
                al[mf][2] = *(const unsigned*)(pl + 8);
                al[mf][3] = *(const unsigned*)(pl + 8*HPAD + 8);
            }

            #pragma unroll
            for (int nfl = 0; nfl < 4; nfl++) {
                uint4 q4 = wc[nfl];
                #pragma unroll
                for (int mf = 0; mf < 2; mf++) {
                    mma_f16(ahh[mf][nfl], ah[mf], q4.x, q4.y);   // hi*hi
                    mma_f16(ahl[mf][nfl], ah[mf], q4.z, q4.w);   // hi*lo(2048)
                    mma_f16(alh[mf][nfl], al[mf], q4.x, q4.y);   // lo(2048)*hi
                }
            }

            #pragma unroll
            for (int nfl = 0; nfl < 4; nfl++) wc[nfl] = wn_[nfl];
        }

        // combine terms, write partial gates: sred[kslice][batch][gate col]
        #pragma unroll
        for (int mf = 0; mf < 2; mf++)
            #pragma unroll
            for (int nfl = 0; nfl < 4; nfl++) {
                int col = (nhalf*4 + nfl)*8 + 2*tig;
                float v0 = ahh[mf][nfl][0] + (ahl[mf][nfl][0] + alh[mf][nfl][0]) * INV2K;
                float v1 = ahh[mf][nfl][1] + (ahl[mf][nfl][1] + alh[mf][nfl][1]) * INV2K;
                float v2 = ahh[mf][nfl][2] + (ahl[mf][nfl][2] + alh[mf][nfl][2]) * INV2K;
                float v3 = ahh[mf][nfl][3] + (ahl[mf][nfl][3] + alh[mf][nfl][3]) * INV2K;
                float* s = sred + (size_t)(kslice*32 + mf*16 + g)*RST2 + col;
                *(float2*)(s)            = make_float2(v0, v1);
                *(float2*)(s + 8*RST2)   = make_float2(v2, v3);
            }
        __syncthreads();

        // reduce 2 K-partials + cell update: each thread 4 cells (b=ub, du=uu*4+i)
        #pragma unroll
        for (int i = 0; i < 4; i++) {
            int du = uu*4 + i;
            float gt[4];
            #pragma unroll
            for (int q = 0; q < 4; q++) {
                int r = q*16 + du;
                gt[q] = gin[i][q]
                      + sred[(size_t)(0*32 + ub)*RST2 + r]
                      + sred[(size_t)(1*32 + ub)*RST2 + r];
            }
            int uidx = ub * HDIM + u0 + du;
            float cc = cst[uidx];
            float si = 1.f / (1.f + expf(-gt[0]));
            float sf = 1.f / (1.f + expf(-gt[1]));
            float so = 1.f / (1.f + expf(-gt[3]));
            float cn = sf * cc + si * tanhf(gt[2]);
            float hn = so * tanhf(cn);
            cst[uidx] = cn;
            hnx[uidx] = hn;
            hout[((size_t)tt * BATCH + ub) * H2 + dir * HDIM + u0 + du] = hn;
        }
        __syncthreads();

        // per-(layer,dir) barrier: monotonic counter, NBLKD arrivals per step
        if (tid == 0) {
            __threadfence();
            atomicAdd(ctr, 1u);
            unsigned target = NBLKD * (unsigned)(t + 1);
            while (*((volatile unsigned*)ctr) < target) { }
            __threadfence();
        }
        __syncthreads();
    }
}

// ---------------- linear + softmax + angle mixture ------------------------------
__global__ void k_angles(const float* __restrict__ Wlin,
                         const float* __restrict__ blin,
                         const float* __restrict__ alpha)
{
    int w = blockIdx.x * (blockDim.x >> 5) + (threadIdx.x >> 5);
    int lane = threadIdx.x & 31;
    const float* hv = g_h2 + (size_t)w * H2;

    float acc[ASZ];
    #pragma unroll
    for (int j = 0; j < ASZ; j++) acc[j] = 0.f;

    for (int kk = 0; kk < H2 / 32; kk++) {
        float h = hv[lane + kk * 32];
        #pragma unroll
        for (int j = 0; j < ASZ; j++)
            acc[j] = fmaf(h, Wlin[(size_t)j * H2 + lane + kk * 32], acc[j]);
    }
    #pragma unroll
    for (int j = 0; j < ASZ; j++) {
        float v = acc[j];
        #pragma unroll
        for (int s = 16; s; s >>= 1) v += __shfl_xor_sync(0xffffffffu, v, s);
        acc[j] = v + blin[j];
    }
    float mx = acc[0];
    #pragma unroll
    for (int j = 1; j < ASZ; j++) mx = fmaxf(mx, acc[j]);
    float sum = 0.f;
    #pragma unroll
    for (int j = 0; j < ASZ; j++) { acc[j] = expf(acc[j] - mx); sum += acc[j]; }
    float inv = 1.f / sum;

    if (lane < 3) {
        float sm = 0.f, cm = 0.f;
        #pragma unroll
        for (int j = 0; j < ASZ; j++) {
            float p = acc[j] * inv;
            float a = alpha[j * 3 + lane];
            sm = fmaf(p, sinf(a), sm);
            cm = fmaf(p, cosf(a), cm);
        }
        float ang = atan2f(sm, cm);
        int t = w / BATCH, b = w % BATCH;
        g_phi[(t * 3 + lane) * BATCH + b] = ang;
    }
}

// ---------------- NeRF ----------------------------------------------------------
__global__ void k_nerf(float* __restrict__ out)
{
    int b = threadIdx.x;
    const float PI_F = 3.14159265358979323846f;
    const float bl[3] = {1.458f, 1.525f, 1.329f};
    const float ba[3] = {2.124f, 1.941f, 2.028f};
    float ct[3], st[3];
    #pragma unroll
    for (int r = 0; r < 3; r++) { float th = PI_F - ba[r]; ct[r] = cosf(th); st[r] = sinf(th); }

    float ax = 0.f, ay = 0.f, az = 0.f;
    float bx = 1.458f, by = 0.f, bz = 0.f;
    float th0 = PI_F - 2.124f;
    float cx = bx + 1.525f * cosf(th0);
    float cy = 1.525f * sinf(th0);
    float cz = 0.f;

    int r = 0;
    #pragma unroll 1
    for (int i = 0; i < L3; i++) {
        float phi = g_phi[i * BATCH + b];
        float vx = cx - bx, vy = cy - by, vz = cz - bz;
        float n1 = sqrtf(vx*vx + vy*vy + vz*vz);
        float s1 = 1.f / (n1 + 1e-8f);
        float bcx = vx * s1, bcy = vy * s1, bcz = vz * s1;
        float ux = bx - ax, uy = by - ay, uz = bz - az;
        float nx = uy * bcz - uz * bcy;
        float ny = uz * bcx - ux * bcz;
        float nz = ux * bcy - uy * bcx;
        float n2 = sqrtf(nx*nx + ny*ny + nz*nz);
        float s2 = 1.f / (n2 + 1e-8f);
        nx *= s2; ny *= s2; nz *= s2;
        float mx = ny * bcz - nz * bcy;
        float my = nz * bcx - nx * bcz;
        float mz = nx * bcy - ny * bcx;

        float sp, cp;
        sincosf(phi, &sp, &cp);
        float d = bl[r];
        float c_t = ct[r], s_t = st[r];

        float wx = cx + d * (c_t * bcx + s_t * (cp * mx + sp * nx));
        float wy = cy + d * (c_t * bcy + s_t * (cp * my + sp * ny));
        float wz = cz + d * (c_t * bcz + s_t * (cp * mz + sp * nz));

        size_t o = ((size_t)i * BATCH + b) * 3;
        out[o + 0] = wx; out[o + 1] = wy; out[o + 2] = wz;

        ax = bx; ay = by; az = bz;
        bx = cx; by = cy; bz = cz;
        cx = wx; cy = wy; cz = wz;
        r = (r == 2) ? 0 : (r + 1);
    }
}

// ---------------- launch --------------------------------------------------------
extern "C" void kernel_launch(void* const* d_in, const int* in_sizes, int n_in,
                              void* d_out, int out_size)
{
    const float* x     = (const float*)d_in[0];
    const float* Wih0f = (const float*)d_in[1];
    const float* Whh0f = (const float*)d_in[2];
    const float* bih0f = (const float*)d_in[3];
    const float* bhh0f = (const float*)d_in[4];
    const float* Wih0b = (const float*)d_in[5];
    const float* Whh0b = (const float*)d_in[6];
    const float* bih0b = (const float*)d_in[7];
    const float* bhh0b = (const float*)d_in[8];
    const float* Wih1f = (const float*)d_in[9];
    const float* Whh1f = (const float*)d_in[10];
    const float* bih1f = (const float*)d_in[11];
    const float* bhh1f = (const float*)d_in[12];
    const float* Wih1b = (const float*)d_in[13];
    const float* Whh1b = (const float*)d_in[14];
    const float* bih1b = (const float*)d_in[15];
    const float* bhh1b = (const float*)d_in[16];
    const float* W_lin = (const float*)d_in[17];
    const float* b_lin = (const float*)d_in[18];
    const float* alpha = (const float*)d_in[19];

    static int s_attr_done = 0;
    if (!s_attr_done) {
        cudaFuncSetAttribute(k_lstm_mma, cudaFuncAttributeMaxDynamicSharedMemorySize, LSTM_SMEM4);
        s_attr_done = 1;
    }

    k_init<<<800, 256>>>();

    // build fp16-split fragment-ordered weights
    k_wfrag<<<dim3(2500, 2), 256>>>(Whh0f, Whh0b, 0);
    k_wfrag<<<dim3(2500, 2), 256>>>(Whh1f, Whh1b, 1);

    k_proj0<<<dim3(512, 16, 2), 256>>>(x, Wih0f, bih0f, bhh0f, Wih0b, bih0b, bhh0b);

    k_lstm_mma<<<2 * NBLKD, 128, LSTM_SMEM4>>>(0);

    k_proj1<<<dim3(G4 / 128, (LSEQ * BATCH) / 128, 2), 256>>>(Wih1f, bih1f, bhh1f,
                                                              Wih1b, bih1b, bhh1b);

    k_lstm_mma<<<2 * NBLKD, 128, LSTM_SMEM4>>>(1);

    k_angles<<<(LSEQ * BATCH) / 8, 256>>>(W_lin, b_lin, alpha);

    k_nerf<<<1, 32>>>((float*)d_out);
}

// round 11
// speedup vs baseline: 1.8051x; 1.0400x over previous
#include <cuda_runtime.h>
#include <cuda_bf16.h>
#include <cuda_fp16.h>
#include <math.h>

#define LSEQ 512
#define BATCH 32
#define DIN 42
#define HDIM 800
#define G4 3200          // 4*HDIM
#define H2 1600          // 2*HDIM
#define ASZ 20
#define L3 (3*LSEQ)

// ---------------- static device scratch (no allocations allowed) ----------------
__device__ float g_G[4][LSEQ*BATCH*G4];
__device__ float g_h1[LSEQ*BATCH*H2];
__device__ float g_h2[LSEQ*BATCH*H2];
__device__ float g_hs[2][2][2][BATCH*HDIM];   // [layer][dir][parity][b*H+u]
__device__ float g_cs[2][2][BATCH*HDIM];      // [layer][dir][b*H+u]
__device__ float g_phi[L3*BATCH];             // [3L][B]
// fp16-split W in mma fragment order:
// [layer][dir][((tile*50 + kt)*8 + nf)*32 + lane] = {b0_hi, b1_hi, b0_lo*2048, b1_lo*2048}
__device__ uint4 g_Wfrag[2][2][50*50*8*32];
// per-(layer,dir) monotonic barrier counters
__device__ unsigned g_ctr[2][2];

// ---------------- init (graph is replayed; must re-zero) ------------------------
__global__ void k_init()
{
    int i = blockIdx.x * blockDim.x + threadIdx.x;
    if (i < 2*2*2*BATCH*HDIM) ((float*)g_hs)[i] = 0.f;
    if (i < 2*2*BATCH*HDIM)   ((float*)g_cs)[i] = 0.f;
    if (i < 4)                ((unsigned*)g_ctr)[i] = 0u;
}

// ---------------- tf32 / fp16 helpers -------------------------------------------
__device__ __forceinline__ unsigned f2tf32(float x)
{
    unsigned r;
    asm("cvt.rna.tf32.f32 %0, %1;" : "=r"(r) : "f"(x));
    return r;
}

__device__ __forceinline__ void mma_tf32(float* d, unsigned a0, unsigned a1, unsigned a2, unsigned a3,
                                         unsigned b0, unsigned b1)
{
    asm volatile("mma.sync.aligned.m16n8k8.row.col.f32.tf32.tf32.f32 "
                 "{%0,%1,%2,%3}, {%4,%5,%6,%7}, {%8,%9}, {%0,%1,%2,%3};"
                 : "+f"(d[0]), "+f"(d[1]), "+f"(d[2]), "+f"(d[3])
                 : "r"(a0), "r"(a1), "r"(a2), "r"(a3), "r"(b0), "r"(b1));
}

__device__ __forceinline__ void mma_f16(float* d, const unsigned* a, unsigned b0, unsigned b1)
{
    asm volatile("mma.sync.aligned.m16n8k16.row.col.f32.f16.f16.f32 "
                 "{%0,%1,%2,%3}, {%4,%5,%6,%7}, {%8,%9}, {%0,%1,%2,%3};"
                 : "+f"(d[0]), "+f"(d[1]), "+f"(d[2]), "+f"(d[3])
                 : "r"(a[0]), "r"(a[1]), "r"(a[2]), "r"(a[3]), "r"(b0), "r"(b1));
}

__device__ __forceinline__ unsigned packh2(half a, half b)
{
    __half2 h = __halves2half2(a, b);
    return *(unsigned*)&h;
}

// ---------------- build fp16-split W fragments ----------------------------------
// grid (2500, 2): blk = tile*50 + kt; 256 threads = 8 nf x 32 lanes
__global__ void k_wfrag(const float* __restrict__ Wf, const float* __restrict__ Wb, int layer)
{
    int dir = blockIdx.y;
    const float* W = dir ? Wb : Wf;
    int blk  = blockIdx.x;
    int tile = blk / 50, kt = blk % 50;
    int tid  = threadIdx.x;
    int nf   = tid >> 5, lane = tid & 31;
    int g    = lane >> 2, tig = lane & 3;
    int r    = nf*8 + g;
    int q    = r >> 4, du = r & 15;
    const float* row = W + (size_t)(q*HDIM + tile*16 + du) * HDIM + kt*16;
    float e0 = row[2*tig], e1 = row[2*tig+1], e2 = row[8+2*tig], e3 = row[9+2*tig];
    half h0 = __float2half_rn(e0); half l0 = __float2half_rn((e0 - __half2float(h0)) * 2048.f);
    half h1 = __float2half_rn(e1); half l1 = __float2half_rn((e1 - __half2float(h1)) * 2048.f);
    half h2 = __float2half_rn(e2); half l2 = __float2half_rn((e2 - __half2float(h2)) * 2048.f);
    half h3 = __float2half_rn(e3); half l3 = __float2half_rn((e3 - __half2float(h3)) * 2048.f);
    uint4 out;
    out.x = packh2(h0, h1);
    out.y = packh2(h2, h3);
    out.z = packh2(l0, l1);
    out.w = packh2(l2, l3);
    g_Wfrag[layer][dir][(size_t)((tile*50 + kt)*8 + nf)*32 + lane] = out;
}

// ---------------- layer0 input projection (W-reuse tiled) -----------------------
__global__ void __launch_bounds__(256)
k_proj0(const float* __restrict__ x,
        const float* __restrict__ Wf, const float* __restrict__ bif, const float* __restrict__ bhf,
        const float* __restrict__ Wb, const float* __restrict__ bib, const float* __restrict__ bhb)
{
    int tb0 = blockIdx.x * 32;
    int j0  = blockIdx.y * 200;
    int dir = blockIdx.z;
    const float* W  = dir ? Wb : Wf;
    const float* b1 = dir ? bib : bif;
    const float* b2 = dir ? bhb : bhf;
    float* G = g_G[dir];

    __shared__ float sx[32*43];
    for (int idx = threadIdx.x; idx < 32*DIN; idx += 256) {
        int tb = idx / DIN, k = idx % DIN;
        sx[tb*43 + k] = x[(size_t)(tb0 + tb)*DIN + k];
    }
    __syncthreads();

    #pragma unroll 1
    for (int i = 0; i < 25; i++) {
        int o  = i*256 + threadIdx.x;
        int j  = o >> 5;
        int tb = o & 31;
        const float* wr = W + (size_t)(j0 + j) * DIN;
        float acc = b1[j0+j] + b2[j0+j];
        #pragma unroll
        for (int k = 0; k < DIN; k++) acc = fmaf(wr[k], sx[tb*43 + k], acc);
        G[(size_t)(tb0 + tb)*G4 + j0 + j] = acc;
    }
}

// ---------------- layer1 input projection: tf32 tensor-core GEMM ----------------
#define PSTR 20
__global__ void __launch_bounds__(256)
k_proj1(const float* __restrict__ Wf, const float* __restrict__ bif, const float* __restrict__ bhf,
        const float* __restrict__ Wb, const float* __restrict__ bib, const float* __restrict__ bhb)
{
    int dir = blockIdx.z;
    const float* Bm = dir ? Wb : Wf;
    const float* b1 = dir ? bib : bif;
    const float* b2 = dir ? bhb : bhf;
    const float* A  = g_h1;
    float* C = g_G[2 + dir];

    int m0 = blockIdx.y * 128;
    int n0 = blockIdx.x * 128;

    __shared__ float Ah[128*PSTR], Al[128*PSTR], Bh[128*PSTR], Bl[128*PSTR];

    int tid  = threadIdx.x;
    int warp = tid >> 5;
    int lane = tid & 31;
    int g    = lane >> 2;
    int tig  = lane & 3;

    int wm = (warp & 3) * 32;
    int wn = (warp >> 2) * 64;

    int lrow = tid >> 1;
    int lkq  = (tid & 1) * 8;

    float acc[2][8][4];
    #pragma unroll
    for (int i = 0; i < 2; i++)
        #pragma unroll
        for (int j = 0; j < 8; j++)
            #pragma unroll
            for (int q = 0; q < 4; q++) acc[i][j][q] = 0.f;

    float4 av0 = *(const float4*)(A  + (size_t)(m0 + lrow)*H2 + 0 + lkq);
    float4 av1 = *(const float4*)(A  + (size_t)(m0 + lrow)*H2 + 0 + lkq + 4);
    float4 bv0 = *(const float4*)(Bm + (size_t)(n0 + lrow)*H2 + 0 + lkq);
    float4 bv1 = *(const float4*)(Bm + (size_t)(n0 + lrow)*H2 + 0 + lkq + 4);

    for (int it = 0; it < 100; it++) {
        {
            float va[8] = {av0.x, av0.y, av0.z, av0.w, av1.x, av1.y, av1.z, av1.w};
            float vb[8] = {bv0.x, bv0.y, bv0.z, bv0.w, bv1.x, bv1.y, bv1.z, bv1.w};
            #pragma unroll
            for (int j = 0; j < 8; j++) {
                float ahi = __uint_as_float(f2tf32(va[j]));
                float alo = __uint_as_float(f2tf32(va[j] - ahi));
                Ah[lrow*PSTR + lkq + j] = ahi;
                Al[lrow*PSTR + lkq + j] = alo;
                float bhi = __uint_as_float(f2tf32(vb[j]));
                float blo = __uint_as_float(f2tf32(vb[j] - bhi));
                Bh[lrow*PSTR + lkq + j] = bhi;
                Bl[lrow*PSTR + lkq + j] = blo;
            }
        }
        __syncthreads();

        if (it < 99) {
            int k0 = (it + 1) * 16;
            av0 = *(const float4*)(A  + (size_t)(m0 + lrow)*H2 + k0 + lkq);
            av1 = *(const float4*)(A  + (size_t)(m0 + lrow)*H2 + k0 + lkq + 4);
            bv0 = *(const float4*)(Bm + (size_t)(n0 + lrow)*H2 + k0 + lkq);
            bv1 = *(const float4*)(Bm + (size_t)(n0 + lrow)*H2 + k0 + lkq + 4);
        }

        #pragma unroll
        for (int kk = 0; kk < 16; kk += 8) {
            unsigned ah[2][4], al[2][4];
            #pragma unroll
            for (int mf = 0; mf < 2; mf++) {
                int r0 = wm + mf*16 + g;
                int r1 = r0 + 8;
                int c0 = kk + tig, c1 = kk + tig + 4;
                ah[mf][0] = __float_as_uint(Ah[r0*PSTR + c0]);
                ah[mf][1] = __float_as_uint(Ah[r1*PSTR + c0]);
                ah[mf][2] = __float_as_uint(Ah[r0*PSTR + c1]);
                ah[mf][3] = __float_as_uint(Ah[r1*PSTR + c1]);
                al[mf][0] = __float_as_uint(Al[r0*PSTR + c0]);
                al[mf][1] = __float_as_uint(Al[r1*PSTR + c0]);
                al[mf][2] = __float_as_uint(Al[r0*PSTR + c1]);
                al[mf][3] = __float_as_uint(Al[r1*PSTR + c1]);
            }
            #pragma unroll
            for (int nf = 0; nf < 8; nf++) {
                int n = wn + nf*8 + g;
                unsigned bh0 = __float_as_uint(Bh[n*PSTR + kk + tig]);
                unsigned bh1 = __float_as_uint(Bh[n*PSTR + kk + tig + 4]);
                unsigned bl0 = __float_as_uint(Bl[n*PSTR + kk + tig]);
                unsigned bl1 = __float_as_uint(Bl[n*PSTR + kk + tig + 4]);
                #pragma unroll
                for (int mf = 0; mf < 2; mf++) {
                    mma_tf32(acc[mf][nf], ah[mf][0], ah[mf][1], ah[mf][2], ah[mf][3], bh0, bh1);
                    mma_tf32(acc[mf][nf], ah[mf][0], ah[mf][1], ah[mf][2], ah[mf][3], bl0, bl1);
                    mma_tf32(acc[mf][nf], al[mf][0], al[mf][1], al[mf][2], al[mf][3], bh0, bh1);
                }
            }
        }
        __syncthreads();
    }

    #pragma unroll
    for (int mf = 0; mf < 2; mf++) {
        int r0 = m0 + wm + mf*16 + g;
        #pragma unroll
        for (int nf = 0; nf < 8; nf++) {
            int col = n0 + wn + nf*8 + 2*tig;
            float bb0 = b1[col]   + b2[col];
            float bb1 = b1[col+1] + b2[col+1];
            float2 v0 = make_float2(acc[mf][nf][0] + bb0, acc[mf][nf][1] + bb1);
            float2 v1 = make_float2(acc[mf][nf][2] + bb0, acc[mf][nf][3] + bb1);
            *(float2*)(C + (size_t)r0*G4 + col)     = v0;
            *(float2*)(C + (size_t)(r0+8)*G4 + col) = v1;
        }
    }
}

// ---------------- persistent bi-LSTM recurrence: fp16 split, 8 warps ------------
// 100 blocks = 50 tiles(16 units) x 2 dirs; 256 threads (2 warps/SMSP); 1 blk/SM.
// Warp w: kslice = w&1 (25 k16-tiles), nq = w>>2? -> nq = w>>1 (0..3): 2 nf frags.
#define NBLKD 50u
#define HPAD 808
#define RST2 68
#define LSTM_SMEM4 (2*32*HPAD*2 + 2*32*RST2*4)
__global__ void __launch_bounds__(256, 1)
k_lstm_mma(int layer)
{
    extern __shared__ char dsmc[];
    half*  hhi  = (half*)dsmc;                 // [32][HPAD]
    half*  hlo  = hhi + 32*HPAD;               // [32][HPAD]  (scaled by 2048)
    float* sred = (float*)(hlo + 32*HPAD);     // [2][32][RST2]

    int dir  = blockIdx.x & 1;
    int tile = blockIdx.x >> 1;
    int u0   = tile * 16;

    const uint4* Wf    = g_Wfrag[layer][dir] + (size_t)tile * 50 * 8 * 32;
    const float* Gbase = g_G[layer*2 + dir];
    float* cst  = g_cs[layer][dir];
    float* hout = layer ? g_h2 : g_h1;
    float* hb0  = g_hs[layer][dir][0];
    float* hb1  = g_hs[layer][dir][1];
    unsigned* ctr = &g_ctr[layer][dir];

    int tid  = threadIdx.x;
    int lane = tid & 31;
    int w    = tid >> 5;          // 0..7
    int g    = lane >> 2;
    int tig  = lane & 3;
    int kslice = w & 1;           // K half
    int nq     = w >> 1;          // 0..3: gate-row quarter (2 nf frags)

    // staging ids: 32 rows x 8 k-eighths(100)
    int sb = tid >> 3;
    int sq = tid & 7;
    // cell ids: 256 threads = 32 batch x 8 unit-pairs
    int ub = tid & 31;
    int uu = tid >> 5;            // 0..7 -> du = uu*2 + i

    const float INV2K = 1.f / 2048.f;

    for (int t = 0; t < LSEQ; t++) {
        int tt = dir ? (LSEQ - 1 - t) : t;
        const float* hin = (t & 1) ? hb1 : hb0;
        float*       hnx = (t & 1) ? hb0 : hb1;
        const float* G   = Gbase + (size_t)tt * (BATCH * G4);

        // prefetch input-gate values: 2 cells x 4 gates via float2
        float2 gin[4];
        #pragma unroll
        for (int q = 0; q < 4; q++)
            gin[q] = *(const float2*)(G + (size_t)ub * G4 + q*HDIM + u0 + uu*2);

        // stage h into smem as fp16 hi/lo (lo scaled by 2048)
        {
            const float* hp = hin + sb * HDIM + sq * 100;
            half* hh = hhi + sb * HPAD + sq * 100;
            half* hl = hlo + sb * HPAD + sq * 100;
            #pragma unroll 5
            for (int j = 0; j < 100; j += 4) {
                float4 v = *(const float4*)(hp + j);
                half a0 = __float2half_rn(v.x); half b0 = __float2half_rn((v.x - __half2float(a0)) * 2048.f);
                half a1 = __float2half_rn(v.y); half b1 = __float2half_rn((v.y - __half2float(a1)) * 2048.f);
                half a2 = __float2half_rn(v.z); half b2 = __float2half_rn((v.z - __half2float(a2)) * 2048.f);
                half a3 = __float2half_rn(v.w); half b3 = __float2half_rn((v.w - __half2float(a3)) * 2048.f);
                *(unsigned*)(hh + j)     = packh2(a0, a1);
                *(unsigned*)(hh + j + 2) = packh2(a2, a3);
                *(unsigned*)(hl + j)     = packh2(b0, b1);
                *(unsigned*)(hl + j + 2) = packh2(b2, b3);
            }
        }
        __syncthreads();

        float ahh[2][2][4], ahl[2][2][4], alh[2][2][4];
        #pragma unroll
        for (int mf = 0; mf < 2; mf++)
            #pragma unroll
            for (int nfl = 0; nfl < 2; nfl++)
                #pragma unroll
                for (int q = 0; q < 4; q++) { ahh[mf][nfl][q] = 0.f; ahl[mf][nfl][q] = 0.f; alh[mf][nfl][q] = 0.f; }

        // W fragment double buffer (2 frags per warp per kt)
        uint4 wc[2], wn_[2];
        #pragma unroll
        for (int nfl = 0; nfl < 2; nfl++)
            wc[nfl] = Wf[(size_t)((kslice*25)*8 + nq*2 + nfl)*32 + lane];

        #pragma unroll 5
        for (int ktl = 0; ktl < 25; ktl++) {
            int kt = kslice*25 + ktl;
            if (ktl < 24) {
                #pragma unroll
                for (int nfl = 0; nfl < 2; nfl++)
                    wn_[nfl] = Wf[(size_t)((kt+1)*8 + nq*2 + nfl)*32 + lane];
            }

            // A fragments from smem (hi and scaled-lo)
            unsigned ah[2][4], al[2][4];
            int k0 = kt * 16;
            #pragma unroll
            for (int mf = 0; mf < 2; mf++) {
                const half* ph = hhi + (mf*16 + g)*HPAD + k0 + 2*tig;
                const half* pl = hlo + (mf*16 + g)*HPAD + k0 + 2*tig;
                ah[mf][0] = *(const unsigned*)(ph);
                ah[mf][1] = *(const unsigned*)(ph + 8*HPAD);
                ah[mf][2] = *(const unsigned*)(ph + 8);
                ah[mf][3] = *(const unsigned*)(ph + 8*HPAD + 8);
                al[mf][0] = *(const unsigned*)(pl);
                al[mf][1] = *(const unsigned*)(pl + 8*HPAD);
                al[mf][2] = *(const unsigned*)(pl + 8);
                al[mf][3] = *(const unsigned*)(pl + 8*HPAD + 8);
            }

            #pragma unroll
            for (int nfl = 0; nfl < 2; nfl++) {
                uint4 q4 = wc[nfl];
                #pragma unroll
                for (int mf = 0; mf < 2; mf++) {
                    mma_f16(ahh[mf][nfl], ah[mf], q4.x, q4.y);   // hi*hi
                    mma_f16(ahl[mf][nfl], ah[mf], q4.z, q4.w);   // hi*lo(2048)
                    mma_f16(alh[mf][nfl], al[mf], q4.x, q4.y);   // lo(2048)*hi
                }
            }

            wc[0] = wn_[0]; wc[1] = wn_[1];
        }

        // combine terms, write partial gates: sred[kslice][batch][gate col]
        #pragma unroll
        for (int mf = 0; mf < 2; mf++)
            #pragma unroll
            for (int nfl = 0; nfl < 2; nfl++) {
                int col = (nq*2 + nfl)*8 + 2*tig;
                float v0 = ahh[mf][nfl][0] + (ahl[mf][nfl][0] + alh[mf][nfl][0]) * INV2K;
                float v1 = ahh[mf][nfl][1] + (ahl[mf][nfl][1] + alh[mf][nfl][1]) * INV2K;
                float v2 = ahh[mf][nfl][2] + (ahl[mf][nfl][2] + alh[mf][nfl][2]) * INV2K;
                float v3 = ahh[mf][nfl][3] + (ahl[mf][nfl][3] + alh[mf][nfl][3]) * INV2K;
                float* s = sred + (size_t)(kslice*32 + mf*16 + g)*RST2 + col;
                *(float2*)(s)            = make_float2(v0, v1);
                *(float2*)(s + 8*RST2)   = make_float2(v2, v3);
            }
        __syncthreads();

        // reduce 2 K-partials + cell update: each thread 2 cells (b=ub, du=uu*2+i)
        #pragma unroll
        for (int i = 0; i < 2; i++) {
            int du = uu*2 + i;
            float gt[4];
            #pragma unroll
            for (int q = 0; q < 4; q++) {
                int r = q*16 + du;
                float gi_ = (i == 0) ? gin[q].x : gin[q].y;
                gt[q] = gi_
                      + sred[(size_t)(0*32 + ub)*RST2 + r]
                      + sred[(size_t)(1*32 + ub)*RST2 + r];
            }
            int uidx = ub * HDIM + u0 + du;
            float cc = cst[uidx];
            float si = 1.f / (1.f + expf(-gt[0]));
            float sf = 1.f / (1.f + expf(-gt[1]));
            float so = 1.f / (1.f + expf(-gt[3]));
            float cn = sf * cc + si * tanhf(gt[2]);
            float hn = so * tanhf(cn);
            cst[uidx] = cn;
            hnx[uidx] = hn;
            hout[((size_t)tt * BATCH + ub) * H2 + dir * HDIM + u0 + du] = hn;
        }
        __syncthreads();

        // per-(layer,dir) barrier: monotonic counter, NBLKD arrivals per step
        if (tid == 0) {
            __threadfence();
            atomicAdd(ctr, 1u);
            unsigned target = NBLKD * (unsigned)(t + 1);
            while (*((volatile unsigned*)ctr) < target) { }
            __threadfence();
        }
        __syncthreads();
    }
}

// ---------------- linear + softmax + angle mixture ------------------------------
__global__ void k_angles(const float* __restrict__ Wlin,
                         const float* __restrict__ blin,
                         const float* __restrict__ alpha)
{
    int w = blockIdx.x * (blockDim.x >> 5) + (threadIdx.x >> 5);
    int lane = threadIdx.x & 31;
    const float* hv = g_h2 + (size_t)w * H2;

    float acc[ASZ];
    #pragma unroll
    for (int j = 0; j < ASZ; j++) acc[j] = 0.f;

    for (int kk = 0; kk < H2 / 32; kk++) {
        float h = hv[lane + kk * 32];
        #pragma unroll
        for (int j = 0; j < ASZ; j++)
            acc[j] = fmaf(h, Wlin[(size_t)j * H2 + lane + kk * 32], acc[j]);
    }
    #pragma unroll
    for (int j = 0; j < ASZ; j++) {
        float v = acc[j];
        #pragma unroll
        for (int s = 16; s; s >>= 1) v += __shfl_xor_sync(0xffffffffu, v, s);
        acc[j] = v + blin[j];
    }
    float mx = acc[0];
    #pragma unroll
    for (int j = 1; j < ASZ; j++) mx = fmaxf(mx, acc[j]);
    float sum = 0.f;
    #pragma unroll
    for (int j = 0; j < ASZ; j++) { acc[j] = expf(acc[j] - mx); sum += acc[j]; }
    float inv = 1.f / sum;

    if (lane < 3) {
        float sm = 0.f, cm = 0.f;
        #pragma unroll
        for (int j = 0; j < ASZ; j++) {
            float p = acc[j] * inv;
            float a = alpha[j * 3 + lane];
            sm = fmaf(p, sinf(a), sm);
            cm = fmaf(p, cosf(a), cm);
        }
        float ang = atan2f(sm, cm);
        int t = w / BATCH, b = w % BATCH;
        g_phi[(t * 3 + lane) * BATCH + b] = ang;
    }
}

// ---------------- NeRF ----------------------------------------------------------
__global__ void k_nerf(float* __restrict__ out)
{
    int b = threadIdx.x;
    const float PI_F = 3.14159265358979323846f;
    const float bl[3] = {1.458f, 1.525f, 1.329f};
    const float ba[3] = {2.124f, 1.941f, 2.028f};
    float ct[3], st[3];
    #pragma unroll
    for (int r = 0; r < 3; r++) { float th = PI_F - ba[r]; ct[r] = cosf(th); st[r] = sinf(th); }

    float ax = 0.f, ay = 0.f, az = 0.f;
    float bx = 1.458f, by = 0.f, bz = 0.f;
    float th0 = PI_F - 2.124f;
    float cx = bx + 1.525f * cosf(th0);
    float cy = 1.525f * sinf(th0);
    float cz = 0.f;

    int r = 0;
    #pragma unroll 1
    for (int i = 0; i < L3; i++) {
        float phi = g_phi[i * BATCH + b];
        float vx = cx - bx, vy = cy - by, vz = cz - bz;
        float n1 = sqrtf(vx*vx + vy*vy + vz*vz);
        float s1 = 1.f / (n1 + 1e-8f);
        float bcx = vx * s1, bcy = vy * s1, bcz = vz * s1;
        float ux = bx - ax, uy = by - ay, uz = bz - az;
        float nx = uy * bcz - uz * bcy;
        float ny = uz * bcx - ux * bcz;
        float nz = ux * bcy - uy * bcx;
        float n2 = sqrtf(nx*nx + ny*ny + nz*nz);
        float s2 = 1.f / (n2 + 1e-8f);
        nx *= s2; ny *= s2; nz *= s2;
        float mx = ny * bcz - nz * bcy;
        float my = nz * bcx - nx * bcz;
        float mz = nx * bcy - ny * bcx;

        float sp, cp;
        sincosf(phi, &sp, &cp);
        float d = bl[r];
        float c_t = ct[r], s_t = st[r];

        float wx = cx + d * (c_t * bcx + s_t * (cp * mx + sp * nx));
        float wy = cy + d * (c_t * bcy + s_t * (cp * my + sp * ny));
        float wz = cz + d * (c_t * bcz + s_t * (cp * mz + sp * nz));

        size_t o = ((size_t)i * BATCH + b) * 3;
        out[o + 0] = wx; out[o + 1] = wy; out[o + 2] = wz;

        ax = bx; ay = by; az = bz;
        bx = cx; by = cy; bz = cz;
        cx = wx; cy = wy; cz = wz;
        r = (r == 2) ? 0 : (r + 1);
    }
}

// ---------------- launch --------------------------------------------------------
extern "C" void kernel_launch(void* const* d_in, const int* in_sizes, int n_in,
                              void* d_out, int out_size)
{
    const float* x     = (const float*)d_in[0];
    const float* Wih0f = (const float*)d_in[1];
    const float* Whh0f = (const float*)d_in[2];
    const float* bih0f = (const float*)d_in[3];
    const float* bhh0f = (const float*)d_in[4];
    const float* Wih0b = (const float*)d_in[5];
    const float* Whh0b = (const float*)d_in[6];
    const float* bih0b = (const float*)d_in[7];
    const float* bhh0b = (const float*)d_in[8];
    const float* Wih1f = (const float*)d_in[9];
    const float* Whh1f = (const float*)d_in[10];
    const float* bih1f = (const float*)d_in[11];
    const float* bhh1f = (const float*)d_in[12];
    const float* Wih1b = (const float*)d_in[13];
    const float* Whh1b = (const float*)d_in[14];
    const float* bih1b = (const float*)d_in[15];
    const float* bhh1b = (const float*)d_in[16];
    const float* W_lin = (const float*)d_in[17];
    const float* b_lin = (const float*)d_in[18];
    const float* alpha = (const float*)d_in[19];

    static int s_attr_done = 0;
    if (!s_attr_done) {
        cudaFuncSetAttribute(k_lstm_mma, cudaFuncAttributeMaxDynamicSharedMemorySize, LSTM_SMEM4);
        s_attr_done = 1;
    }

    k_init<<<800, 256>>>();

    // build fp16-split fragment-ordered weights
    k_wfrag<<<dim3(2500, 2), 256>>>(Whh0f, Whh0b, 0);
    k_wfrag<<<dim3(2500, 2), 256>>>(Whh1f, Whh1b, 1);

    k_proj0<<<dim3(512, 16, 2), 256>>>(x, Wih0f, bih0f, bhh0f, Wih0b, bih0b, bhh0b);

    k_lstm_mma<<<2 * NBLKD, 256, LSTM_SMEM4>>>(0);

    k_proj1<<<dim3(G4 / 128, (LSEQ * BATCH) / 128, 2), 256>>>(Wih1f, bih1f, bhh1f,
                                                              Wih1b, bih1b, bhh1b);

    k_lstm_mma<<<2 * NBLKD, 256, LSTM_SMEM4>>>(1);

    k_angles<<<(LSEQ * BATCH) / 8, 256>>>(W_lin, b_lin, alpha);

    k_nerf<<<1, 32>>>((float*)d_out);
}

// round 16
// speedup vs baseline: 2.2718x; 1.2585x over previous
#include <cuda_runtime.h>
#include <cuda_bf16.h>
#include <cuda_fp16.h>
#include <stdint.h>
#include <math.h>

#define LSEQ 512
#define BATCH 32
#define DIN 42
#define HDIM 800
#define G4 3200          // 4*HDIM
#define H2 1600          // 2*HDIM
#define ASZ 20
#define L3 (3*LSEQ)

// ---------------- static device scratch (no allocations allowed) ----------------
// G layout: [t][q][u][b]  -> index ((t*4 + q)*800 + u)*32 + b
__device__ float g_G[4][LSEQ*4*HDIM*BATCH];
__device__ float g_h1[LSEQ*BATCH*H2];
__device__ float g_h2[LSEQ*BATCH*H2];
__device__ float g_hs[2][2][2][BATCH*HDIM];   // [layer][dir][parity][b*H+u]
__device__ float g_cs[2][2][BATCH*HDIM];      // [layer][dir][b*H+u]
__device__ float g_phi[L3*BATCH];             // [3L][B]
// fp16-split Whh fragments (recurrence), mma fragment order
__device__ uint4 g_Wfrag[2][2][50*50*8*32];
// fp16-split Wih1 fragments (proj1), mma fragment order:
// [dir][((nt*100 + kt)*16 + nf)*32 + lane]
__device__ uint4 g_W1frag[2][25*100*16*32];
// fp16-split h1 [m][k] layout
__device__ __half g_h1h[LSEQ*BATCH*H2];
__device__ __half g_h1l[LSEQ*BATCH*H2];       // scaled by 2048
// per-(layer,dir) monotonic barrier counters
__device__ unsigned g_ctr[2][2];

// ---------------- init (graph is replayed; must re-zero) ------------------------
__global__ void k_init()
{
    int i = blockIdx.x * blockDim.x + threadIdx.x;
    if (i < 2*2*2*BATCH*HDIM) ((float*)g_hs)[i] = 0.f;
    if (i < 2*2*BATCH*HDIM)   ((float*)g_cs)[i] = 0.f;
    if (i < 4)                ((unsigned*)g_ctr)[i] = 0u;
}

// ---------------- helpers -------------------------------------------------------
__device__ __forceinline__ void mma_f16(float* d, const unsigned* a, unsigned b0, unsigned b1)
{
    asm volatile("mma.sync.aligned.m16n8k16.row.col.f32.f16.f16.f32 "
                 "{%0,%1,%2,%3}, {%4,%5,%6,%7}, {%8,%9}, {%0,%1,%2,%3};"
                 : "+f"(d[0]), "+f"(d[1]), "+f"(d[2]), "+f"(d[3])
                 : "r"(a[0]), "r"(a[1]), "r"(a[2]), "r"(a[3]), "r"(b0), "r"(b1));
}

__device__ __forceinline__ unsigned packh2(__half a, __half b)
{
    __half2 h = __halves2half2(a, b);
    return *(unsigned*)&h;
}

// ---------------- build fp16-split Whh fragments (recurrence) -------------------
__global__ void k_wfrag(const float* __restrict__ Wf, const float* __restrict__ Wb, int layer)
{
    int dir = blockIdx.y;
    const float* W = dir ? Wb : Wf;
    int blk  = blockIdx.x;
    int tile = blk / 50, kt = blk % 50;
    int tid  = threadIdx.x;
    int nf   = tid >> 5, lane = tid & 31;
    int g    = lane >> 2, tig = lane & 3;
    int r    = nf*8 + g;
    int q    = r >> 4, du = r & 15;
    const float* row = W + (size_t)(q*HDIM + tile*16 + du) * HDIM + kt*16;
    float e0 = row[2*tig], e1 = row[2*tig+1], e2 = row[8+2*tig], e3 = row[9+2*tig];
    __half h0 = __float2half_rn(e0); __half l0 = __float2half_rn((e0 - __half2float(h0)) * 2048.f);
    __half h1 = __float2half_rn(e1); __half l1 = __float2half_rn((e1 - __half2float(h1)) * 2048.f);
    __half h2 = __float2half_rn(e2); __half l2 = __float2half_rn((e2 - __half2float(h2)) * 2048.f);
    __half h3 = __float2half_rn(e3); __half l3 = __float2half_rn((e3 - __half2float(h3)) * 2048.f);
    uint4 out;
    out.x = packh2(h0, h1);
    out.y = packh2(h2, h3);
    out.z = packh2(l0, l1);
    out.w = packh2(l2, l3);
    g_Wfrag[layer][dir][(size_t)((tile*50 + kt)*8 + nf)*32 + lane] = out;
}

// ---------------- build fp16-split Wih1 fragments (proj1) -----------------------
// grid (2500, 2): blk = nt*100 + kt; 512 threads = 16 nf x 32 lanes
__global__ void k_wfrag1(const float* __restrict__ Wf, const float* __restrict__ Wb)
{
    int dir = blockIdx.y;
    const float* W = dir ? Wb : Wf;
    int blk = blockIdx.x;
    int nt = blk / 100, kt = blk % 100;
    int tid = threadIdx.x;
    int nf = tid >> 5, lane = tid & 31;
    int g = lane >> 2, tig = lane & 3;
    int r = nt*128 + nf*8 + g;
    const float* row = W + (size_t)r * H2 + kt*16;
    float e0 = row[2*tig], e1 = row[2*tig+1], e2 = row[8+2*tig], e3 = row[9+2*tig];
    __half h0 = __float2half_rn(e0); __half l0 = __float2half_rn((e0 - __half2float(h0)) * 2048.f);
    __half h1 = __float2half_rn(e1); __half l1 = __float2half_rn((e1 - __half2float(h1)) * 2048.f);
    __half h2 = __float2half_rn(e2); __half l2 = __float2half_rn((e2 - __half2float(h2)) * 2048.f);
    __half h3 = __float2half_rn(e3); __half l3 = __float2half_rn((e3 - __half2float(h3)) * 2048.f);
    uint4 out;
    out.x = packh2(h0, h1);
    out.y = packh2(h2, h3);
    out.z = packh2(l0, l1);
    out.w = packh2(l2, l3);
    g_W1frag[dir][(size_t)((nt*100 + kt)*16 + nf)*32 + lane] = out;
}

// ---------------- split h1 -> fp16 hi/lo ([m][k] layout) ------------------------
__global__ void k_h1split()
{
    size_t i = ((size_t)blockIdx.x * 256 + threadIdx.x) * 8;
    float4 v0 = *(const float4*)(g_h1 + i);
    float4 v1 = *(const float4*)(g_h1 + i + 4);
    float vv[8] = {v0.x, v0.y, v0.z, v0.w, v1.x, v1.y, v1.z, v1.w};
    __half hh[8], hl[8];
    #pragma unroll
    for (int j = 0; j < 8; j++) {
        hh[j] = __float2half_rn(vv[j]);
        hl[j] = __float2half_rn((vv[j] - __half2float(hh[j])) * 2048.f);
    }
    uint4 oh, ol;
    oh.x = packh2(hh[0], hh[1]); oh.y = packh2(hh[2], hh[3]);
    oh.z = packh2(hh[4], hh[5]); oh.w = packh2(hh[6], hh[7]);
    ol.x = packh2(hl[0], hl[1]); ol.y = packh2(hl[2], hl[3]);
    ol.z = packh2(hl[4], hl[5]); ol.w = packh2(hl[6], hl[7]);
    *(uint4*)(g_h1h + i) = oh;
    *(uint4*)(g_h1l + i) = ol;
}

// ---------------- layer0 input projection (coalesced new-layout writes) ---------
__global__ void __launch_bounds__(256)
k_proj0(const float* __restrict__ x,
        const float* __restrict__ Wf, const float* __restrict__ bif, const float* __restrict__ bhf,
        const float* __restrict__ Wb, const float* __restrict__ bib, const float* __restrict__ bhb)
{
    int t   = blockIdx.x;            // one t per block (32 b)
    int j0  = blockIdx.y * 200;
    int dir = blockIdx.z;
    const float* W  = dir ? Wb : Wf;
    const float* b1 = dir ? bib : bif;
    const float* b2 = dir ? bhb : bhf;
    float* G = g_G[dir];

    __shared__ float sx[32*43];
    for (int idx = threadIdx.x; idx < 32*DIN; idx += 256) {
        int tb = idx / DIN, k = idx % DIN;
        sx[tb*43 + k] = x[((size_t)t*32 + tb)*DIN + k];
    }
    __syncthreads();

    #pragma unroll 1
    for (int i = 0; i < 25; i++) {
        int o  = i*256 + threadIdx.x;
        int j  = o >> 5;                 // warp-uniform
        int tb = o & 31;
        int col = j0 + j;
        int q = col / HDIM, u = col % HDIM;
        const float* wr = W + (size_t)col * DIN;
        float acc = b1[col] + b2[col];
        #pragma unroll
        for (int k = 0; k < DIN; k++) acc = fmaf(wr[k], sx[tb*43 + k], acc);
        G[(((size_t)t*4 + q)*HDIM + u)*32 + tb] = acc;
    }
}

// ---------------- layer1 input projection: fp16-split mma.sync GEMM -------------
// grid (25 nt, 128 mt, 2 dir), 512 threads (16 warps, warp tile 32x32).
#define PH 24   // A smem stride in halves (conflict-free)
__global__ void __launch_bounds__(512, 1)
k_proj1h(const float* __restrict__ bif, const float* __restrict__ bhf,
         const float* __restrict__ bib, const float* __restrict__ bhb)
{
    static __shared__ char psm[24576];   // A double buffer (hi/lo); reused as T

    int tid = threadIdx.x;
    int dir = blockIdx.z;
    int n0  = blockIdx.x * 128;
    int m0  = blockIdx.y * 128;
    int t0  = blockIdx.y * 4;

    const float* b1 = dir ? bib : bif;
    const float* b2 = dir ? bhb : bhf;
    const uint4* Wfr = g_W1frag[dir] + (size_t)blockIdx.x * 100 * 16 * 32;
    float* C = g_G[2 + dir];

    int warp = tid >> 5, lane = tid & 31;
    int g = lane >> 2, tig = lane & 3;
    int wm = (warp & 3) * 32;
    int wnf0 = (warp >> 2) * 4;          // 4 nf frags (32 cols)

    // staging ids
    int srow  = tid >> 2;
    int spart = (tid >> 1) & 1;
    int sarr  = tid & 1;
    const __half* sbase = sarr ? g_h1l : g_h1h;

    float acc_h[2][4][4], acc_c[2][4][4];
    #pragma unroll
    for (int mf = 0; mf < 2; mf++)
        #pragma unroll
        for (int nf = 0; nf < 4; nf++)
            #pragma unroll
            for (int q = 0; q < 4; q++) { acc_h[mf][nf][q] = 0.f; acc_c[mf][nf][q] = 0.f; }

    #define P1H_STAGE(kt_, buf_) do {                                                  \
        uint4 v_ = *(const uint4*)(sbase + (size_t)(m0 + srow)*H2 + (kt_)*16 + spart*8);\
        *(uint4*)((__half*)psm + ((buf_)*2 + sarr)*(128*PH) + srow*PH + spart*8) = v_;  \
    } while (0)

    P1H_STAGE(0, 0);
    __syncthreads();

    for (int kt = 0; kt < 100; kt++) {
        int buf = kt & 1;
        if (kt < 99) P1H_STAGE(kt + 1, buf ^ 1);

        uint4 wq[4];
        const uint4* wrow = Wfr + (size_t)kt*16*32 + wnf0*32 + lane;
        #pragma unroll
        for (int nf = 0; nf < 4; nf++) wq[nf] = wrow[nf*32];

        const __half* Ah = (__half*)psm + (buf*2 + 0)*(128*PH);
        const __half* Al = (__half*)psm + (buf*2 + 1)*(128*PH);
        unsigned ah[2][4], al[2][4];
        #pragma unroll
        for (int mf = 0; mf < 2; mf++) {
            const __half* p = Ah + (wm + mf*16 + g)*PH + 2*tig;
            const __half* pl = Al + (wm + mf*16 + g)*PH + 2*tig;
            ah[mf][0] = *(const unsigned*)(p);
            ah[mf][1] = *(const unsigned*)(p + 8*PH);
            ah[mf][2] = *(const unsigned*)(p + 8);
            ah[mf][3] = *(const unsigned*)(p + 8*PH + 8);
            al[mf][0] = *(const unsigned*)(pl);
            al[mf][1] = *(const unsigned*)(pl + 8*PH);
            al[mf][2] = *(const unsigned*)(pl + 8);
            al[mf][3] = *(const unsigned*)(pl + 8*PH + 8);
        }
        #pragma unroll
        for (int nf = 0; nf < 4; nf++) {
            uint4 q4 = wq[nf];
            #pragma unroll
            for (int mf = 0; mf < 2; mf++) {
                mma_f16(acc_h[mf][nf], ah[mf], q4.x, q4.y);   // hi*hi
                mma_f16(acc_c[mf][nf], ah[mf], q4.z, q4.w);   // hi*lo(2048)
                mma_f16(acc_c[mf][nf], al[mf], q4.x, q4.y);   // lo(2048)*hi
            }
        }
        __syncthreads();
    }

    // epilogue: transpose via smem, write coalesced into G'[t][q][u][b]
    float* T = (float*)psm;  // [128][33]
    const float INV2K = 1.f / 2048.f;
    int wnc = warp >> 2;     // this warp's 32-col chunk (0..3)
    int pair = tid >> 2;     // 0..127: (tt, colc)
    int ttn = pair >> 5, colc = pair & 31;
    int l4 = tid & 3;        // b-subrange

    #pragma unroll 1
    for (int c = 0; c < 4; c++) {
        if (wnc == c) {
            #pragma unroll
            for (int mf = 0; mf < 2; mf++)
                #pragma unroll
                for (int nf = 0; nf < 4; nf++) {
                    int r0 = wm + mf*16 + g;
                    int cc = nf*8 + 2*tig;
                    T[r0*33 + cc]       = acc_h[mf][nf][0] + acc_c[mf][nf][0]*INV2K;
                    T[r0*33 + cc + 1]   = acc_h[mf][nf][1] + acc_c[mf][nf][1]*INV2K;
                    T[(r0+8)*33 + cc]   = acc_h[mf][nf][2] + acc_c[mf][nf][2]*INV2K;
                    T[(r0+8)*33 + cc+1] = acc_h[mf][nf][3] + acc_c[mf][nf][3]*INV2K;
                }
        }
        __syncthreads();
        {
            int colg = n0 + c*32 + colc;
            int q = colg / HDIM, u = colg % HDIM;
            float bias = b1[colg] + b2[colg];
            float* dst = C + ((((size_t)(t0 + ttn))*4 + q)*HDIM + u)*32 + l4*8;
            float4 v0, v1;
            int rb = ttn*32 + l4*8;
            v0.x = T[(rb+0)*33 + colc] + bias;
            v0.y = T[(rb+1)*33 + colc] + bias;
            v0.z = T[(rb+2)*33 + colc] + bias;
            v0.w = T[(rb+3)*33 + colc] + bias;
            v1.x = T[(rb+4)*33 + colc] + bias;
            v1.y = T[(rb+5)*33 + colc] + bias;
            v1.z = T[(rb+6)*33 + colc] + bias;
            v1.w = T[(rb+7)*33 + colc] + bias;
            *(float4*)dst = v0;
            *(float4*)(dst + 4) = v1;
        }
        __syncthreads();
    }
}

// ---------------- persistent bi-LSTM recurrence: fp16 split, 8 warps ------------
#define NBLKD 50u
#define HPAD 808
#define RST2 68
#define LSTM_SMEM4 ((2*32*HPAD)*2 + (2*32*RST2)*4 + 2048*4)
__global__ void __launch_bounds__(256, 1)
k_lstm_mma(int layer)
{
    extern __shared__ char dsmc[];
    __half* hhi = (__half*)dsmc;               // [32][HPAD]
    __half* hlo = hhi + 32*HPAD;               // [32][HPAD]  (scaled by 2048)
    float* sred = (float*)(hlo + 32*HPAD);     // [2][32][RST2]
    float* sgin = sred + 2*32*RST2;            // [4][16][32]

    int dir  = blockIdx.x & 1;
    int tile = blockIdx.x >> 1;
    int u0   = tile * 16;

    const uint4* Wf    = g_Wfrag[layer][dir] + (size_t)tile * 50 * 8 * 32;
    const float* Gbase = g_G[layer*2 + dir];
    float* cst  = g_cs[layer][dir];
    float* hout = layer ? g_h2 : g_h1;
    float* hb0  = g_hs[layer][dir][0];
    float* hb1  = g_hs[layer][dir][1];
    unsigned* ctr = &g_ctr[layer][dir];

    int tid  = threadIdx.x;
    int lane = tid & 31;
    int w    = tid >> 5;
    int g    = lane >> 2;
    int tig  = lane & 3;
    int kslice = w & 1;
    int nq     = w >> 1;

    int sb = tid >> 3;
    int sq = tid & 7;
    int ub = tid & 31;
    int uu = tid >> 5;

    // gin staging ids: 4 q-chunks of 512 contiguous floats
    int qg = tid >> 6;
    int f8 = (tid & 63) * 8;

    const float INV2K = 1.f / 2048.f;

    for (int t = 0; t < LSEQ; t++) {
        int tt = dir ? (LSEQ - 1 - t) : t;
        const float* hin = (t & 1) ? hb1 : hb0;
        float*       hnx = (t & 1) ? hb0 : hb1;
        const float* Gt  = Gbase + (size_t)tt * (4*HDIM*32);

        // issue gin loads early (contiguous 2KB chunk per q)
        const float* gp = Gt + ((size_t)qg*HDIM + u0)*32 + f8;
        float4 ga = *(const float4*)gp;
        float4 gb = *(const float4*)(gp + 4);

        // stage h into smem as fp16 hi/lo (lo scaled by 2048)
        {
            const float* hp = hin + sb * HDIM + sq * 100;
            __half* hh = hhi + sb * HPAD + sq * 100;
            __half* hl = hlo + sb * HPAD + sq * 100;
            #pragma unroll 5
            for (int j = 0; j < 100; j += 4) {
                float4 v = *(const float4*)(hp + j);
                __half a0 = __float2half_rn(v.x); __half b0 = __float2half_rn((v.x - __half2float(a0)) * 2048.f);
                __half a1 = __float2half_rn(v.y); __half b1 = __float2half_rn((v.y - __half2float(a1)) * 2048.f);
                __half a2 = __float2half_rn(v.z); __half b2 = __float2half_rn((v.z - __half2float(a2)) * 2048.f);
                __half a3 = __float2half_rn(v.w); __half b3 = __float2half_rn((v.w - __half2float(a3)) * 2048.f);
                *(unsigned*)(hh + j)     = packh2(a0, a1);
                *(unsigned*)(hh + j + 2) = packh2(a2, a3);
                *(unsigned*)(hl + j)     = packh2(b0, b1);
                *(unsigned*)(hl + j + 2) = packh2(b2, b3);
            }
        }
        // park gin in smem
        *(float4*)(sgin + qg*512 + f8)     = ga;
        *(float4*)(sgin + qg*512 + f8 + 4) = gb;
        __syncthreads();

        float ahh[2][2][4], ahl[2][2][4], alh[2][2][4];
        #pragma unroll
        for (int mf = 0; mf < 2; mf++)
            #pragma unroll
            for (int nfl = 0; nfl < 2; nfl++)
                #pragma unroll
                for (int q = 0; q < 4; q++) { ahh[mf][nfl][q] = 0.f; ahl[mf][nfl][q] = 0.f; alh[mf][nfl][q] = 0.f; }

        uint4 wc[2], wn_[2];
        #pragma unroll
        for (int nfl = 0; nfl < 2; nfl++)
            wc[nfl] = Wf[(size_t)((kslice*25)*8 + nq*2 + nfl)*32 + lane];

        #pragma unroll 5
        for (int ktl = 0; ktl < 25; ktl++) {
            int kt = kslice*25 + ktl;
            if (ktl < 24) {
                #pragma unroll
                for (int nfl = 0; nfl < 2; nfl++)
                    wn_[nfl] = Wf[(size_t)((kt+1)*8 + nq*2 + nfl)*32 + lane];
            }

            unsigned ah[2][4], al[2][4];
            int k0 = kt * 16;
            #pragma unroll
            for (int mf = 0; mf < 2; mf++) {
                const __half* ph = hhi + (mf*16 + g)*HPAD + k0 + 2*tig;
                const __half* pl = hlo + (mf*16 + g)*HPAD + k0 + 2*tig;
                ah[mf][0] = *(const unsigned*)(ph);
                ah[mf][1] = *(const unsigned*)(ph + 8*HPAD);
                ah[mf][2] = *(const unsigned*)(ph + 8);
                ah[mf][3] = *(const unsigned*)(ph + 8*HPAD + 8);
                al[mf][0] = *(const unsigned*)(pl);
                al[mf][1] = *(const unsigned*)(pl + 8*HPAD);
                al[mf][2] = *(const unsigned*)(pl + 8);
                al[mf][3] = *(const unsigned*)(pl + 8*HPAD + 8);
            }

            #pragma unroll
            for (int nfl = 0; nfl < 2; nfl++) {
                uint4 q4 = wc[nfl];
                #pragma unroll
                for (int mf = 0; mf < 2; mf++) {
                    mma_f16(ahh[mf][nfl], ah[mf], q4.x, q4.y);
                    mma_f16(ahl[mf][nfl], ah[mf], q4.z, q4.w);
                    mma_f16(alh[mf][nfl], al[mf], q4.x, q4.y);
                }
            }

            wc[0] = wn_[0]; wc[1] = wn_[1];
        }

        #pragma unroll
        for (int mf = 0; mf < 2; mf++)
            #pragma unroll
            for (int nfl = 0; nfl < 2; nfl++) {
                int col = (nq*2 + nfl)*8 + 2*tig;
                float v0 = ahh[mf][nfl][0] + (ahl[mf][nfl][0] + alh[mf][nfl][0]) * INV2K;
                float v1 = ahh[mf][nfl][1] + (ahl[mf][nfl][1] + alh[mf][nfl][1]) * INV2K;
                float v2 = ahh[mf][nfl][2] + (ahl[mf][nfl][2] + alh[mf][nfl][2]) * INV2K;
                float v3 = ahh[mf][nfl][3] + (ahl[mf][nfl][3] + alh[mf][nfl][3]) * INV2K;
                float* s = sred + (size_t)(kslice*32 + mf*16 + g)*RST2 + col;
                *(float2*)(s)            = make_float2(v0, v1);
                *(float2*)(s + 8*RST2)   = make_float2(v2, v3);
            }
        __syncthreads();

        #pragma unroll
        for (int i = 0; i < 2; i++) {
            int du = uu*2 + i;
            float gt[4];
            #pragma unroll
            for (int q = 0; q < 4; q++) {
                int r = q*16 + du;
                gt[q] = sgin[q*512 + du*32 + ub]
                      + sred[(size_t)(0*32 + ub)*RST2 + r]
                      + sred[(size_t)(1*32 + ub)*RST2 + r];
            }
            int uidx = ub * HDIM + u0 + du;
            float cc = cst[uidx];
            float si = 1.f / (1.f + expf(-gt[0]));
            float sf = 1.f / (1.f + expf(-gt[1]));
            float so = 1.f / (1.f + expf(-gt[3]));
            float cn = sf * cc + si * tanhf(gt[2]);
            float hn = so * tanhf(cn);
            cst[uidx] = cn;
            hnx[uidx] = hn;
            hout[((size_t)tt * BATCH + ub) * H2 + dir * HDIM + u0 + du] = hn;
        }
        __syncthreads();

        if (tid == 0) {
            __threadfence();
            atomicAdd(ctr, 1u);
            unsigned target = NBLKD * (unsigned)(t + 1);
            while (*((volatile unsigned*)ctr) < target) { }
            __threadfence();
        }
        __syncthreads();
    }
}

// ---------------- linear + softmax + angle mixture ------------------------------
__global__ void k_angles(const float* __restrict__ Wlin,
                         const float* __restrict__ blin,
                         const float* __restrict__ alpha)
{
    int w = blockIdx.x * (blockDim.x >> 5) + (threadIdx.x >> 5);
    int lane = threadIdx.x & 31;
    const float* hv = g_h2 + (size_t)w * H2;

    float acc[ASZ];
    #pragma unroll
    for (int j = 0; j < ASZ; j++) acc[j] = 0.f;

    for (int kk = 0; kk < H2 / 32; kk++) {
        float h = hv[lane + kk * 32];
        #pragma unroll
        for (int j = 0; j < ASZ; j++)
            acc[j] = fmaf(h, Wlin[(size_t)j * H2 + lane + kk * 32], acc[j]);
    }
    #pragma unroll
    for (int j = 0; j < ASZ; j++) {
        float v = acc[j];
        #pragma unroll
        for (int s = 16; s; s >>= 1) v += __shfl_xor_sync(0xffffffffu, v, s);
        acc[j] = v + blin[j];
    }
    float mx = acc[0];
    #pragma unroll
    for (int j = 1; j < ASZ; j++) mx = fmaxf(mx, acc[j]);
    float sum = 0.f;
    #pragma unroll
    for (int j = 0; j < ASZ; j++) { acc[j] = expf(acc[j] - mx); sum += acc[j]; }
    float inv = 1.f / sum;

    if (lane < 3) {
        float sm = 0.f, cm = 0.f;
        #pragma unroll
        for (int j = 0; j < ASZ; j++) {
            float p = acc[j] * inv;
            float a = alpha[j * 3 + lane];
            sm = fmaf(p, sinf(a), sm);
            cm = fmaf(p, cosf(a), cm);
        }
        float ang = atan2f(sm, cm);
        int t = w / BATCH, b = w % BATCH;
        g_phi[(t * 3 + lane) * BATCH + b] = ang;
    }
}

// ---------------- NeRF ----------------------------------------------------------
__global__ void k_nerf(float* __restrict__ out)
{
    int b = threadIdx.x;
    const float PI_F = 3.14159265358979323846f;
    const float bl[3] = {1.458f, 1.525f, 1.329f};
    const float ba[3] = {2.124f, 1.941f, 2.028f};
    float ct[3], st[3];
    #pragma unroll
    for (int r = 0; r < 3; r++) { float th = PI_F - ba[r]; ct[r] = cosf(th); st[r] = sinf(th); }

    float ax = 0.f, ay = 0.f, az = 0.f;
    float bx = 1.458f, by = 0.f, bz = 0.f;
    float th0 = PI_F - 2.124f;
    float cx = bx + 1.525f * cosf(th0);
    float cy = 1.525f * sinf(th0);
    float cz = 0.f;

    int r = 0;
    #pragma unroll 1
    for (int i = 0; i < L3; i++) {
        float phi = g_phi[i * BATCH + b];
        float vx = cx - bx, vy = cy - by, vz = cz - bz;
        float n1 = sqrtf(vx*vx + vy*vy + vz*vz);
        float s1 = 1.f / (n1 + 1e-8f);
        float bcx = vx * s1, bcy = vy * s1, bcz = vz * s1;
        float ux = bx - ax, uy = by - ay, uz = bz - az;
        float nx = uy * bcz - uz * bcy;
        float ny = uz * bcx - ux * bcz;
        float nz = ux * bcy - uy * bcx;
        float n2 = sqrtf(nx*nx + ny*ny + nz*nz);
        float s2 = 1.f / (n2 + 1e-8f);
        nx *= s2; ny *= s2; nz *= s2;
        float mx = ny * bcz - nz * bcy;
        float my = nz * bcx - nx * bcz;
        float mz = nx * bcy - ny * bcx;

        float sp, cp;
        sincosf(phi, &sp, &cp);
        float d = bl[r];
        float c_t = ct[r], s_t = st[r];

        float wx = cx + d * (c_t * bcx + s_t * (cp * mx + sp * nx));
        float wy = cy + d * (c_t * bcy + s_t * (cp * my + sp * ny));
        float wz = cz + d * (c_t * bcz + s_t * (cp * mz + sp * nz));

        size_t o = ((size_t)i * BATCH + b) * 3;
        out[o + 0] = wx; out[o + 1] = wy; out[o + 2] = wz;

        ax = bx; ay = by; az = bz;
        bx = cx; by = cy; bz = cz;
        cx = wx; cy = wy; cz = wz;
        r = (r == 2) ? 0 : (r + 1);
    }
}

// ---------------- launch --------------------------------------------------------
extern "C" void kernel_launch(void* const* d_in, const int* in_sizes, int n_in,
                              void* d_out, int out_size)
{
    const float* x     = (const float*)d_in[0];
    const float* Wih0f = (const float*)d_in[1];
    const float* Whh0f = (const float*)d_in[2];
    const float* bih0f = (const float*)d_in[3];
    const float* bhh0f = (const float*)d_in[4];
    const float* Wih0b = (const float*)d_in[5];
    const float* Whh0b = (const float*)d_in[6];
    const float* bih0b = (const float*)d_in[7];
    const float* bhh0b = (const float*)d_in[8];
    const float* Wih1f = (const float*)d_in[9];
    const float* Whh1f = (const float*)d_in[10];
    const float* bih1f = (const float*)d_in[11];
    const float* bhh1f = (const float*)d_in[12];
    const float* Wih1b = (const float*)d_in[13];
    const float* Whh1b = (const float*)d_in[14];
    const float* bih1b = (const float*)d_in[15];
    const float* bhh1b = (const float*)d_in[16];
    const float* W_lin = (const float*)d_in[17];
    const float* b_lin = (const float*)d_in[18];
    const float* alpha = (const float*)d_in[19];

    static int s_attr_done = 0;
    if (!s_attr_done) {
        cudaFuncSetAttribute(k_lstm_mma, cudaFuncAttributeMaxDynamicSharedMemorySize, LSTM_SMEM4);
        s_attr_done = 1;
    }

    k_init<<<800, 256>>>();

    // pre-split weights into fragment order
    k_wfrag<<<dim3(2500, 2), 256>>>(Whh0f, Whh0b, 0);
    k_wfrag<<<dim3(2500, 2), 256>>>(Whh1f, Whh1b, 1);
    k_wfrag1<<<dim3(2500, 2), 512>>>(Wih1f, Wih1b);

    k_proj0<<<dim3(LSEQ, 16, 2), 256>>>(x, Wih0f, bih0f, bhh0f, Wih0b, bih0b, bhh0b);

    // 6th launch: layer-0 recurrence (so ncu -s 5 captures it)
    k_lstm_mma<<<2 * NBLKD, 256, LSTM_SMEM4>>>(0);

    // split h1 to fp16 hi/lo, then fp16 tensor-core layer-1 projection
    k_h1split<<<(LSEQ*BATCH*H2)/(256*8), 256>>>();
    k_proj1h<<<dim3(25, 128, 2), 512>>>(bih1f, bhh1f, bih1b, bhh1b);

    k_lstm_mma<<<2 * NBLKD, 256, LSTM_SMEM4>>>(1);

    k_angles<<<(LSEQ * BATCH) / 8, 256>>>(W_lin, b_lin, alpha);

    k_nerf<<<1, 32>>>((float*)d_out);
}